// round 12
// baseline (speedup 1.0000x reference)
#include <cuda_runtime.h>
#include <cuda_bf16.h>
#include <cstdint>
#include <math.h>

// ---------------- problem constants ----------------
#define S_LEN 4032
#define S_PAD 4096
#define DIMN  1536
#define NHEAD 12
#define HD    128
#define FF    9
#define HHG   16
#define WWG   28
#define CF    22
#define CHH   21
#define CWW   21

#define QK_SCALE_LOG2E ((float)(1.4426950408889634 * 0.08838834764831845))

// ---------------- scratch ----------------
__device__ float g_Q[S_PAD * DIMN];
__device__ float g_K[S_PAD * DIMN];
__device__ unsigned short g_qh[S_PAD * DIMN], g_ql[S_PAD * DIMN];
__device__ unsigned short g_kh[S_PAD * DIMN], g_kl[S_PAD * DIMN];
__device__ unsigned short g_vh[S_PAD * DIMN], g_vl[S_PAD * DIMN];
__device__ unsigned short g_oh[S_PAD * DIMN], g_ol[S_PAD * DIMN];
__device__ unsigned short g_xh[S_PAD * DIMN], g_xl[S_PAD * DIMN];
__device__ unsigned short g_wqh[DIMN * DIMN], g_wql[DIMN * DIMN];
__device__ unsigned short g_wkh[DIMN * DIMN], g_wkl[DIMN * DIMN];
__device__ unsigned short g_wvh[DIMN * DIMN], g_wvl[DIMN * DIMN];
__device__ unsigned short g_woh[DIMN * DIMN], g_wol[DIMN * DIMN];

// ---------------- helpers ----------------
__device__ __forceinline__ uint32_t smem_to_u32(const void* p) {
    uint32_t a;
    asm("{ .reg .u64 t; cvta.to.shared.u64 t, %1; cvt.u32.u64 %0, t; }" : "=r"(a) : "l"(p));
    return a;
}
#define SWZ128(off) ((off) ^ (((off) >> 3) & 0x70))

__device__ __forceinline__ void ldsm_x4(uint32_t* r, uint32_t addr) {
    asm volatile("ldmatrix.sync.aligned.m8n8.x4.shared.b16 {%0,%1,%2,%3}, [%4];"
                 : "=r"(r[0]), "=r"(r[1]), "=r"(r[2]), "=r"(r[3]) : "r"(addr));
}
__device__ __forceinline__ void ldsm_x2(uint32_t* r, uint32_t addr) {
    asm volatile("ldmatrix.sync.aligned.m8n8.x2.shared.b16 {%0,%1}, [%2];"
                 : "=r"(r[0]), "=r"(r[1]) : "r"(addr));
}
__device__ __forceinline__ void ldsm_x2_t(uint32_t* r, uint32_t addr) {
    asm volatile("ldmatrix.sync.aligned.m8n8.x2.trans.shared.b16 {%0,%1}, [%2];"
                 : "=r"(r[0]), "=r"(r[1]) : "r"(addr));
}
__device__ __forceinline__ void mma_bf16(float* c, const uint32_t* a, const uint32_t* b) {
    asm volatile("mma.sync.aligned.m16n8k16.row.col.f32.bf16.bf16.f32 "
                 "{%0,%1,%2,%3}, {%4,%5,%6,%7}, {%8,%9}, {%0,%1,%2,%3};"
                 : "+f"(c[0]), "+f"(c[1]), "+f"(c[2]), "+f"(c[3])
                 : "r"(a[0]), "r"(a[1]), "r"(a[2]), "r"(a[3]), "r"(b[0]), "r"(b[1]));
}
__device__ __forceinline__ float ex2f(float x) {
    float y; asm("ex2.approx.f32 %0, %1;" : "=f"(y) : "f"(x)); return y;
}
__device__ __forceinline__ uint32_t pack_bf2(float x, float y) {
    uint32_t d; asm("cvt.rn.bf16x2.f32 %0, %1, %2;" : "=r"(d) : "f"(y), "f"(x)); return d;
}
__device__ __forceinline__ void split2(float x, float y, uint32_t& hi, uint32_t& lo) {
    hi = pack_bf2(x, y);
    float hx = __uint_as_float(hi << 16);
    float hy = __uint_as_float(hi & 0xffff0000u);
    lo = pack_bf2(x - hx, y - hy);
}
__device__ __forceinline__ void cp_async16(uint32_t saddr, const void* g) {
    asm volatile("cp.async.cg.shared.global [%0], [%1], 16;" :: "r"(saddr), "l"(g) : "memory");
}

// ============================================================================
// split fp32 -> bf16 hi/lo
// ============================================================================
__global__ __launch_bounds__(256) void split_kernel(
    const float* __restrict__ src, unsigned short* __restrict__ hi,
    unsigned short* __restrict__ lo, int n_valid, int n_total)
{
    int i = (blockIdx.x * 256 + threadIdx.x) * 2;
    if (i >= n_total) return;
    float2 v = (i < n_valid) ? *(const float2*)(src + i) : make_float2(0.f, 0.f);
    uint32_t h, l;
    split2(v.x, v.y, h, l);
    *(unsigned int*)(hi + i) = h;
    *(unsigned int*)(lo + i) = l;
}

// ============================================================================
// mma.sync bf16x3 GEMM (unchanged from R4)
// ============================================================================
#define SM_AH  0
#define SM_AL  16384
#define SM_BH  32768
#define SM_BL  49152
#define GEMM_SMEM 65536
#define NCHUNK (DIMN / 64)

__global__ __launch_bounds__(256, 2) void gemm_tc(
    const unsigned short* __restrict__ Ahi, const unsigned short* __restrict__ Alo,
    const unsigned short* __restrict__ Bhi, const unsigned short* __restrict__ Blo,
    const float* __restrict__ bias, float* __restrict__ C,
    unsigned short* __restrict__ Chi, unsigned short* __restrict__ Clo, int Mvalid)
{
    extern __shared__ __align__(1024) char smem[];
    const uint32_t sb = smem_to_u32(smem);
    const int tid  = threadIdx.x;
    const int lane = tid & 31;
    const int wid  = tid >> 5;
    const int wm   = wid & 1;
    const int wn   = wid >> 1;
    const int bm = blockIdx.y * 128;
    const int bn = blockIdx.x * 128;

    const int r0 = tid >> 3;
    const int c8 = tid & 7;
    const uint32_t st_off = SWZ128((uint32_t)(r0 * 128 + c8 * 16));

    uint32_t aoff[4], akey[4];
#pragma unroll
    for (int mf = 0; mf < 4; ++mf) {
        int arow = wm * 64 + mf * 16 + (lane & 15);
        aoff[mf] = (uint32_t)(arow * 128);
        akey[mf] = (uint32_t)((arow & 7) << 4);
    }
    uint32_t boff[4], bkey[4];
    {
        int l = lane & 15;
#pragma unroll
        for (int nf = 0; nf < 4; ++nf) {
            int brow = wn * 32 + nf * 8 + (l & 7);
            boff[nf] = (uint32_t)(brow * 128);
            bkey[nf] = (uint32_t)((brow & 7) << 4);
        }
    }
    const uint32_t abit = (uint32_t)((lane >> 4) << 4);
    const uint32_t bbit = (uint32_t)((((lane & 15) >> 3) & 1) << 4);

    float acc[4][4][4];
#pragma unroll
    for (int mf = 0; mf < 4; ++mf)
#pragma unroll
        for (int nf = 0; nf < 4; ++nf)
#pragma unroll
            for (int e = 0; e < 4; ++e) acc[mf][nf][e] = 0.f;

    for (int chunk = 0; chunk < NCHUNK; ++chunk) {
        const int k0 = chunk * 64;
        __syncthreads();
        {
            const unsigned short* srcs[4] = {Ahi, Alo, Bhi, Blo};
            const int rowbase[4] = {bm, bm, bn, bn};
            const uint32_t dsts[4] = {SM_AH, SM_AL, SM_BH, SM_BL};
#pragma unroll
            for (int t = 0; t < 4; ++t) {
                const unsigned short* s = srcs[t] + (size_t)(rowbase[t] + r0) * DIMN + k0 + c8 * 8;
                char* d = smem + dsts[t] + st_off;
#pragma unroll
                for (int i = 0; i < 4; ++i)
                    *(uint4*)(d + i * 4096) = *(const uint4*)(s + (size_t)(i * 32) * DIMN);
            }
        }
        __syncthreads();

#pragma unroll
        for (int ks = 0; ks < 4; ++ks) {
            const uint32_t kb = (uint32_t)(ks * 32);
            uint32_t bh[4][2], bl[4][2];
#pragma unroll
            for (int nf = 0; nf < 4; ++nf) {
                uint32_t ad = sb + SM_BH + boff[nf] + ((kb + bbit) ^ bkey[nf]);
                ldsm_x2(bh[nf], ad);
                ldsm_x2(bl[nf], ad + (SM_BL - SM_BH));
            }
#pragma unroll
            for (int mf = 0; mf < 4; ++mf) {
                uint32_t ah[4], al[4];
                uint32_t ad = sb + SM_AH + aoff[mf] + ((kb + abit) ^ akey[mf]);
                ldsm_x4(ah, ad);
                ldsm_x4(al, ad + (SM_AL - SM_AH));
#pragma unroll
                for (int nf = 0; nf < 4; ++nf) {
                    mma_bf16(acc[mf][nf], ah, bh[nf]);
                    mma_bf16(acc[mf][nf], ah, bl[nf]);
                    mma_bf16(acc[mf][nf], al, bh[nf]);
                }
            }
        }
    }

    const int row0 = bm + wm * 64 + (lane >> 2);
    const int col0 = bn + wn * 32 + (lane & 3) * 2;
#pragma unroll
    for (int nf = 0; nf < 4; ++nf) {
        const int c = col0 + nf * 8;
        const float2 bb = *(const float2*)(bias + c);
#pragma unroll
        for (int mf = 0; mf < 4; ++mf) {
            const int r = row0 + mf * 16;
            if (Chi) {
                uint32_t h, l;
                if (r < Mvalid) {
                    split2(acc[mf][nf][0] + bb.x, acc[mf][nf][1] + bb.y, h, l);
                    *(unsigned int*)(Chi + (size_t)r * DIMN + c) = h;
                    *(unsigned int*)(Clo + (size_t)r * DIMN + c) = l;
                }
                if (r + 8 < Mvalid) {
                    split2(acc[mf][nf][2] + bb.x, acc[mf][nf][3] + bb.y, h, l);
                    *(unsigned int*)(Chi + (size_t)(r + 8) * DIMN + c) = h;
                    *(unsigned int*)(Clo + (size_t)(r + 8) * DIMN + c) = l;
                }
            } else {
                if (r < Mvalid) {
                    float2 v; v.x = acc[mf][nf][0] + bb.x; v.y = acc[mf][nf][1] + bb.y;
                    *(float2*)(C + (size_t)r * DIMN + c) = v;
                }
                if (r + 8 < Mvalid) {
                    float2 v; v.x = acc[mf][nf][2] + bb.x; v.y = acc[mf][nf][3] + bb.y;
                    *(float2*)(C + (size_t)(r + 8) * DIMN + c) = v;
                }
            }
        }
    }
}

// ============================================================================
// Fused RMSNorm + 3D RoPE (unchanged)
// ============================================================================
__global__ __launch_bounds__(256) void rmsrope_kernel(
    const float* __restrict__ Qm, const float* __restrict__ Km,
    const float* __restrict__ gq, const float* __restrict__ gk,
    const float* __restrict__ cf, const float* __restrict__ sf,
    const float* __restrict__ ch, const float* __restrict__ sh,
    const float* __restrict__ cw, const float* __restrict__ sw,
    unsigned short* __restrict__ qh, unsigned short* __restrict__ ql,
    unsigned short* __restrict__ kh, unsigned short* __restrict__ kl)
{
    const int s = blockIdx.x;
    const int tid = threadIdx.x;
    const int f  = s / (HHG * WWG);
    const int rm = s - f * (HHG * WWG);
    const int hh = rm / WWG;
    const int ww = rm - hh * WWG;

    float co[3], si[3];
#pragma unroll
    for (int p = 0; p < 3; ++p) {
        int c = (tid * 3 + p) & 63;
        if (c < CF)            { co[p] = cf[f  * CF  + c];              si[p] = sf[f  * CF  + c]; }
        else if (c < CF + CHH) { co[p] = ch[hh * CHH + (c - CF)];       si[p] = sh[hh * CHH + (c - CF)]; }
        else                   { co[p] = cw[ww * CWW + (c - CF - CHH)]; si[p] = sw[ww * CWW + (c - CF - CHH)]; }
    }

    __shared__ float red[8];
    __shared__ float bcast;

    for (int which = 0; which < 2; ++which) {
        const float* T = which ? Km : Qm;
        const float* g = which ? gk : gq;
        unsigned short* oh = which ? kh : qh;
        unsigned short* ol = which ? kl : ql;
        const float post = which ? 1.0f : QK_SCALE_LOG2E;
        const size_t base = (size_t)s * DIMN + tid * 6;

        float v[6];
#pragma unroll
        for (int p = 0; p < 3; ++p) {
            float2 t = *(const float2*)(T + base + 2 * p);
            v[2 * p] = t.x; v[2 * p + 1] = t.y;
        }
        float ss = 0.f;
#pragma unroll
        for (int e = 0; e < 6; ++e) ss += v[e] * v[e];
        for (int off = 16; off; off >>= 1) ss += __shfl_xor_sync(0xffffffffu, ss, off);
        if ((tid & 31) == 0) red[tid >> 5] = ss;
        __syncthreads();
        if (tid < 32) {
            float t = (tid < 8) ? red[tid] : 0.f;
            for (int off = 4; off; off >>= 1) t += __shfl_xor_sync(0xffffffffu, t, off);
            if (tid == 0) bcast = t;
        }
        __syncthreads();
        const float rinv = rsqrtf(bcast * (1.0f / DIMN) + 1e-6f);

#pragma unroll
        for (int p = 0; p < 3; ++p) {
            float e = v[2 * p]     * rinv * g[tid * 6 + 2 * p];
            float o = v[2 * p + 1] * rinv * g[tid * 6 + 2 * p + 1];
            float rx = (e * co[p] - o * si[p]) * post;
            float ry = (e * si[p] + o * co[p]) * post;
            uint32_t hw, lw;
            split2(rx, ry, hw, lw);
            *(unsigned int*)(oh + base + 2 * p) = hw;
            *(unsigned int*)(ol + base + 2 * p) = lw;
        }
        __syncthreads();
    }
}

// ============================================================================
// Flash attention, HMMA bf16x3. 256 threads, 2 CTAs/SM (4 warps/SMSP).
// BQ=64, BK=32. 8 warps = 4 q-tiles(16 rows) x 2 key-halves(16 of 32 keys).
// Q hi/lo resident in smem (32KB); K/V hi/lo double-buffered (2x32KB).
// Per-warp online softmax over its key subset; pairwise m/l/O merge at end.
// ============================================================================
#define F2_QH   0
#define F2_QL   16384
#define F2_ST0  32768
#define F2_KH   0
#define F2_KL   8192
#define F2_VH   16384
#define F2_VL   24576
#define F2_ML   98304
#define FLASH2_SMEM (98304 + 2048)
#define NKT2 (S_LEN / 32)   // 126

__global__ __launch_bounds__(256, 2) void flash_tc2(
    const unsigned short* __restrict__ qh_, const unsigned short* __restrict__ ql_,
    const unsigned short* __restrict__ kh_, const unsigned short* __restrict__ kl_,
    const unsigned short* __restrict__ vh_, const unsigned short* __restrict__ vl_,
    unsigned short* __restrict__ oh_, unsigned short* __restrict__ ol_)
{
    extern __shared__ __align__(1024) char sm[];
    const uint32_t sb = smem_to_u32(sm);
    const int tid = threadIdx.x;
    const int lane = tid & 31;
    const int w = tid >> 5;         // 0..7
    const int nh = w & 1;           // key-half
    const int qm = w >> 1;          // q-tile 0..3
    const int l15 = lane & 15;
    const int h = blockIdx.y;
    const int q0 = blockIdx.x * 64;

    // ---- stage Q (hi/lo) resident: 64 rows x 128 cols, 2 chunks of [64][64c] ----
    {
        const unsigned short* srcs[2] = {qh_, ql_};
#pragma unroll
        for (int hl = 0; hl < 2; ++hl) {
            const unsigned short* s = srcs[hl];
#pragma unroll
            for (int i = 0; i < 4; ++i) {
                int idx = tid + i * 256;
                int qr = idx >> 4, c16 = idx & 15;
                uint4 v = *(const uint4*)(s + (size_t)(q0 + qr) * DIMN + h * HD + c16 * 8);
                uint32_t off = (uint32_t)(hl * 16384 + (c16 >> 3) * 8192)
                             + SWZ128((uint32_t)(qr * 128 + (c16 & 7) * 16));
                *(uint4*)(sm + off) = v;
            }
        }
    }

    // ---- K/V stage loader: 4 tiles x [32 rows][128 cols], 2 chunks of 4KB ----
    const int srow = tid >> 3;      // 0..31
    const int sc8 = tid & 7;
    const uint32_t so0 = SWZ128((uint32_t)(srow * 128 + sc8 * 16));
    auto issue_stage = [&](int kt, int st) {
        const int key0 = kt * 32;
        const unsigned short* srcs[4] = {kh_, kl_, vh_, vl_};
        uint32_t base = sb + (uint32_t)(F2_ST0 + st * 32768);
#pragma unroll
        for (int t = 0; t < 4; ++t) {
            const unsigned short* sp = srcs[t] + (size_t)(key0 + srow) * DIMN + h * HD;
            cp_async16(base + (uint32_t)(t * 8192) + so0, sp + sc8 * 8);
            cp_async16(base + (uint32_t)(t * 8192 + 4096) + so0, sp + (sc8 + 8) * 8);
        }
        asm volatile("cp.async.commit_group;" ::: "memory");
    };

    float oacc[16][4];
#pragma unroll
    for (int nt = 0; nt < 16; ++nt)
#pragma unroll
        for (int e = 0; e < 4; ++e) oacc[nt][e] = 0.f;
    float mrow0 = -1e30f, mrow1 = -1e30f, lrow0 = 0.f, lrow1 = 0.f;

    // Q addressing
    const int qrow = qm * 16 + l15;
    const uint32_t qrowb = (uint32_t)(qrow * 128);
    const uint32_t qc8sel = (uint32_t)(lane >> 4);

    issue_stage(0, 0);

    for (int kt = 0; kt < NKT2; ++kt) {
        const int st = kt & 1;
        if (kt < NKT2 - 1) {
            issue_stage(kt + 1, st ^ 1);
            asm volatile("cp.async.wait_group 1;" ::: "memory");
        } else {
            asm volatile("cp.async.wait_group 0;" ::: "memory");
        }
        __syncthreads();

        const uint32_t stb = sb + (uint32_t)(F2_ST0 + st * 32768);

        // ---- scores: 16 q-rows x 16 k-cols (this warp's half) ----
        float sc[2][4];
        sc[0][0] = sc[0][1] = sc[0][2] = sc[0][3] = 0.f;
        sc[1][0] = sc[1][1] = sc[1][2] = sc[1][3] = 0.f;

#pragma unroll
        for (int ks = 0; ks < 8; ++ks) {
            const uint32_t qaddr = sb + (uint32_t)((ks >> 2) * 8192)
                + SWZ128(qrowb + (uint32_t)(((ks & 3) * 2 + qc8sel) * 16));
            uint32_t qh4[4], ql4[4];
            ldsm_x4(qh4, qaddr);
            ldsm_x4(ql4, qaddr + F2_QL);
            const uint32_t kchunk = (uint32_t)((ks >> 2) * 4096);
            const uint32_t kc8 = (uint32_t)(((ks & 3) * 2 + ((l15 >> 3) & 1)) * 16);
#pragma unroll
            for (int nt = 0; nt < 2; ++nt) {
                const uint32_t krow = (uint32_t)((nh * 16 + nt * 8 + (l15 & 7)) * 128);
                uint32_t addr = stb + F2_KH + kchunk + SWZ128(krow + kc8);
                uint32_t bh[2], bl[2];
                ldsm_x2(bh, addr);
                ldsm_x2(bl, addr + (F2_KL - F2_KH));
                mma_bf16(sc[nt], qh4, bh);
                mma_bf16(sc[nt], qh4, bl);
                mma_bf16(sc[nt], ql4, bh);
            }
        }

        // ---- online softmax (log2 units), per-warp key subset ----
        float mx0 = fmaxf(fmaxf(sc[0][0], sc[0][1]), fmaxf(sc[1][0], sc[1][1]));
        float mx1 = fmaxf(fmaxf(sc[0][2], sc[0][3]), fmaxf(sc[1][2], sc[1][3]));
        mx0 = fmaxf(mx0, __shfl_xor_sync(0xffffffffu, mx0, 1));
        mx0 = fmaxf(mx0, __shfl_xor_sync(0xffffffffu, mx0, 2));
        mx1 = fmaxf(mx1, __shfl_xor_sync(0xffffffffu, mx1, 1));
        mx1 = fmaxf(mx1, __shfl_xor_sync(0xffffffffu, mx1, 2));
        const float mn0 = fmaxf(mrow0, mx0);
        const float mn1 = fmaxf(mrow1, mx1);
        const float al0 = ex2f(mrow0 - mn0);
        const float al1 = ex2f(mrow1 - mn1);
        mrow0 = mn0; mrow1 = mn1;
        float rs0 = 0.f, rs1 = 0.f;
#pragma unroll
        for (int nt = 0; nt < 2; ++nt) {
            sc[nt][0] = ex2f(sc[nt][0] - mn0); rs0 += sc[nt][0];
            sc[nt][1] = ex2f(sc[nt][1] - mn0); rs0 += sc[nt][1];
            sc[nt][2] = ex2f(sc[nt][2] - mn1); rs1 += sc[nt][2];
            sc[nt][3] = ex2f(sc[nt][3] - mn1); rs1 += sc[nt][3];
        }
        rs0 += __shfl_xor_sync(0xffffffffu, rs0, 1);
        rs0 += __shfl_xor_sync(0xffffffffu, rs0, 2);
        rs1 += __shfl_xor_sync(0xffffffffu, rs1, 1);
        rs1 += __shfl_xor_sync(0xffffffffu, rs1, 2);
        lrow0 = lrow0 * al0 + rs0;
        lrow1 = lrow1 * al1 + rs1;
        if (al0 != 1.0f || al1 != 1.0f) {
#pragma unroll
            for (int nt = 0; nt < 16; ++nt) {
                oacc[nt][0] *= al0; oacc[nt][1] *= al0;
                oacc[nt][2] *= al1; oacc[nt][3] *= al1;
            }
        }

        // ---- pack P (16x16) into one A-frag group (hi/lo) ----
        uint32_t pah[4], pal[4];
        split2(sc[0][0], sc[0][1], pah[0], pal[0]);
        split2(sc[0][2], sc[0][3], pah[1], pal[1]);
        split2(sc[1][0], sc[1][1], pah[2], pal[2]);
        split2(sc[1][2], sc[1][3], pah[3], pal[3]);

        // ---- O += P @ V (this warp's 16 keys) ----
        const uint32_t vrow = (uint32_t)((nh * 16 + ((l15 >> 3) & 1) * 8 + (l15 & 7)) * 128);
#pragma unroll
        for (int nt = 0; nt < 16; ++nt) {
            uint32_t addr = stb + F2_VH + (uint32_t)((nt >> 3) * 4096)
                          + SWZ128(vrow + (uint32_t)((nt & 7) * 16));
            uint32_t bh[2], bl[2];
            ldsm_x2_t(bh, addr);
            ldsm_x2_t(bl, addr + (F2_VL - F2_VH));
            mma_bf16(oacc[nt], pah, bh);
            mma_bf16(oacc[nt], pah, bl);
            mma_bf16(oacc[nt], pal, bh);
        }
        __syncthreads();
    }

    // ---- merge key-half pairs: nh=1 publishes, nh=0 merges & writes ----
    __syncthreads();
    if (nh == 1) {
        float* dst = (float*)(sm + F2_ST0) + qm * 2048 + lane * 64;
#pragma unroll
        for (int nt = 0; nt < 16; ++nt) {
            dst[nt * 4 + 0] = oacc[nt][0];
            dst[nt * 4 + 1] = oacc[nt][1];
            dst[nt * 4 + 2] = oacc[nt][2];
            dst[nt * 4 + 3] = oacc[nt][3];
        }
        float* ml = (float*)(sm + F2_ML) + qm * 128 + lane * 4;
        ml[0] = mrow0; ml[1] = lrow0; ml[2] = mrow1; ml[3] = lrow1;
    }
    __syncthreads();
    if (nh == 0) {
        const float* src = (const float*)(sm + F2_ST0) + qm * 2048 + lane * 64;
        const float* ml = (const float*)(sm + F2_ML) + qm * 128 + lane * 4;
        const float m1 = ml[0], l1 = ml[1], m1b = ml[2], l1b = ml[3];
        const float M0 = fmaxf(mrow0, m1);
        const float M1 = fmaxf(mrow1, m1b);
        const float a0 = ex2f(mrow0 - M0), b0 = ex2f(m1 - M0);
        const float a1 = ex2f(mrow1 - M1), b1 = ex2f(m1b - M1);
        const float inv0 = 1.0f / (lrow0 * a0 + l1 * b0);
        const float inv1 = 1.0f / (lrow1 * a1 + l1b * b1);

        const int r0 = q0 + qm * 16 + (lane >> 2);
        const int cbase = h * HD + (lane & 3) * 2;
#pragma unroll
        for (int nt = 0; nt < 16; ++nt) {
            const int c = cbase + nt * 8;
            float v0 = (oacc[nt][0] * a0 + src[nt * 4 + 0] * b0) * inv0;
            float v1 = (oacc[nt][1] * a0 + src[nt * 4 + 1] * b0) * inv0;
            float v2 = (oacc[nt][2] * a1 + src[nt * 4 + 2] * b1) * inv1;
            float v3 = (oacc[nt][3] * a1 + src[nt * 4 + 3] * b1) * inv1;
            uint32_t hw, lw;
            split2(v0, v1, hw, lw);
            *(unsigned int*)(oh_ + (size_t)r0 * DIMN + c) = hw;
            *(unsigned int*)(ol_ + (size_t)r0 * DIMN + c) = lw;
            split2(v2, v3, hw, lw);
            *(unsigned int*)(oh_ + (size_t)(r0 + 8) * DIMN + c) = hw;
            *(unsigned int*)(ol_ + (size_t)(r0 + 8) * DIMN + c) = lw;
        }
    }
}

// ============================================================================
// launch
// ============================================================================
extern "C" void kernel_launch(void* const* d_in, const int* in_sizes, int n_in,
                              void* d_out, int out_size)
{
    const float* x  = (const float*)d_in[0];
    const float* Wq = (const float*)d_in[1];
    const float* bq = (const float*)d_in[2];
    const float* Wk = (const float*)d_in[3];
    const float* bk = (const float*)d_in[4];
    const float* Wv = (const float*)d_in[5];
    const float* bv = (const float*)d_in[6];
    const float* Wo = (const float*)d_in[7];
    const float* bo = (const float*)d_in[8];
    const float* gq = (const float*)d_in[9];
    const float* gk = (const float*)d_in[10];
    const float* cf = (const float*)d_in[11];
    const float* sf = (const float*)d_in[12];
    const float* ch = (const float*)d_in[13];
    const float* sh = (const float*)d_in[14];
    const float* cw = (const float*)d_in[15];
    const float* sw = (const float*)d_in[16];
    float* out = (float*)d_out;

    float *Qd, *Kd;
    unsigned short *qh, *ql, *kh, *kl, *vh, *vl, *oh, *ol, *xh, *xl;
    unsigned short *wqh, *wql, *wkh, *wkl, *wvh, *wvl, *woh, *wol;
    cudaGetSymbolAddress((void**)&Qd, g_Q);
    cudaGetSymbolAddress((void**)&Kd, g_K);
    cudaGetSymbolAddress((void**)&qh, g_qh);  cudaGetSymbolAddress((void**)&ql, g_ql);
    cudaGetSymbolAddress((void**)&kh, g_kh);  cudaGetSymbolAddress((void**)&kl, g_kl);
    cudaGetSymbolAddress((void**)&vh, g_vh);  cudaGetSymbolAddress((void**)&vl, g_vl);
    cudaGetSymbolAddress((void**)&oh, g_oh);  cudaGetSymbolAddress((void**)&ol, g_ol);
    cudaGetSymbolAddress((void**)&xh, g_xh);  cudaGetSymbolAddress((void**)&xl, g_xl);
    cudaGetSymbolAddress((void**)&wqh, g_wqh); cudaGetSymbolAddress((void**)&wql, g_wql);
    cudaGetSymbolAddress((void**)&wkh, g_wkh); cudaGetSymbolAddress((void**)&wkl, g_wkl);
    cudaGetSymbolAddress((void**)&wvh, g_wvh); cudaGetSymbolAddress((void**)&wvl, g_wvl);
    cudaGetSymbolAddress((void**)&woh, g_woh); cudaGetSymbolAddress((void**)&wol, g_wol);

    cudaFuncSetAttribute(gemm_tc,
                         cudaFuncAttributeMaxDynamicSharedMemorySize, GEMM_SMEM);
    cudaFuncSetAttribute(flash_tc2,
                         cudaFuncAttributeMaxDynamicSharedMemorySize, FLASH2_SMEM);

    const int NW = DIMN * DIMN;
    const int NXV = S_LEN * DIMN;
    const int NXT = S_PAD * DIMN;

    split_kernel<<<NXT / 512, 256>>>(x, xh, xl, NXV, NXT);
    split_kernel<<<NW / 512, 256>>>(Wq, wqh, wql, NW, NW);
    split_kernel<<<NW / 512, 256>>>(Wk, wkh, wkl, NW, NW);
    split_kernel<<<NW / 512, 256>>>(Wv, wvh, wvl, NW, NW);
    split_kernel<<<NW / 512, 256>>>(Wo, woh, wol, NW, NW);

    dim3 ggrid(DIMN / 128, S_PAD / 128);
    gemm_tc<<<ggrid, 256, GEMM_SMEM>>>(xh, xl, wqh, wql, bq, Qd, nullptr, nullptr, S_PAD);
    gemm_tc<<<ggrid, 256, GEMM_SMEM>>>(xh, xl, wkh, wkl, bk, Kd, nullptr, nullptr, S_PAD);
    gemm_tc<<<ggrid, 256, GEMM_SMEM>>>(xh, xl, wvh, wvl, bv, nullptr, vh, vl, S_PAD);

    rmsrope_kernel<<<S_LEN, 256>>>(Qd, Kd, gq, gk, cf, sf, ch, sh, cw, sw,
                                   qh, ql, kh, kl);

    flash_tc2<<<dim3(S_LEN / 64, NHEAD), 256, FLASH2_SMEM>>>(qh, ql, kh, kl, vh, vl, oh, ol);

    gemm_tc<<<ggrid, 256, GEMM_SMEM>>>(oh, ol, woh, wol, bo, out, nullptr, nullptr, S_LEN);
}

// round 13
// speedup vs baseline: 1.0003x; 1.0003x over previous
#include <cuda_runtime.h>
#include <cuda_bf16.h>
#include <cstdint>
#include <math.h>

// ---------------- problem constants ----------------
#define S_LEN 4032
#define S_PAD 4096
#define DIMN  1536
#define NHEAD 12
#define HD    128
#define FF    9
#define HHG   16
#define WWG   28
#define CF    22
#define CHH   21
#define CWW   21

#define QK_SCALE_LOG2E ((float)(1.4426950408889634 * 0.08838834764831845))

// ---------------- scratch ----------------
__device__ float g_Q[S_PAD * DIMN];
__device__ float g_K[S_PAD * DIMN];
__device__ unsigned short g_qh[S_PAD * DIMN], g_ql[S_PAD * DIMN];
__device__ unsigned short g_kh[S_PAD * DIMN], g_kl[S_PAD * DIMN];
__device__ unsigned short g_vh[S_PAD * DIMN], g_vl[S_PAD * DIMN];
__device__ unsigned short g_oh[S_PAD * DIMN], g_ol[S_PAD * DIMN];
__device__ unsigned short g_xh[S_PAD * DIMN], g_xl[S_PAD * DIMN];
__device__ unsigned short g_wqh[DIMN * DIMN], g_wql[DIMN * DIMN];
__device__ unsigned short g_wkh[DIMN * DIMN], g_wkl[DIMN * DIMN];
__device__ unsigned short g_wvh[DIMN * DIMN], g_wvl[DIMN * DIMN];
__device__ unsigned short g_woh[DIMN * DIMN], g_wol[DIMN * DIMN];

// ---------------- helpers ----------------
__device__ __forceinline__ uint32_t smem_to_u32(const void* p) {
    uint32_t a;
    asm("{ .reg .u64 t; cvta.to.shared.u64 t, %1; cvt.u32.u64 %0, t; }" : "=r"(a) : "l"(p));
    return a;
}
#define SWZ128(off) ((off) ^ (((off) >> 3) & 0x70))

__device__ __forceinline__ void ldsm_x4(uint32_t* r, uint32_t addr) {
    asm volatile("ldmatrix.sync.aligned.m8n8.x4.shared.b16 {%0,%1,%2,%3}, [%4];"
                 : "=r"(r[0]), "=r"(r[1]), "=r"(r[2]), "=r"(r[3]) : "r"(addr));
}
__device__ __forceinline__ void ldsm_x2(uint32_t* r, uint32_t addr) {
    asm volatile("ldmatrix.sync.aligned.m8n8.x2.shared.b16 {%0,%1}, [%2];"
                 : "=r"(r[0]), "=r"(r[1]) : "r"(addr));
}
__device__ __forceinline__ void ldsm_x2_t(uint32_t* r, uint32_t addr) {
    asm volatile("ldmatrix.sync.aligned.m8n8.x2.trans.shared.b16 {%0,%1}, [%2];"
                 : "=r"(r[0]), "=r"(r[1]) : "r"(addr));
}
__device__ __forceinline__ void mma_bf16(float* c, const uint32_t* a, const uint32_t* b) {
    asm volatile("mma.sync.aligned.m16n8k16.row.col.f32.bf16.bf16.f32 "
                 "{%0,%1,%2,%3}, {%4,%5,%6,%7}, {%8,%9}, {%0,%1,%2,%3};"
                 : "+f"(c[0]), "+f"(c[1]), "+f"(c[2]), "+f"(c[3])
                 : "r"(a[0]), "r"(a[1]), "r"(a[2]), "r"(a[3]), "r"(b[0]), "r"(b[1]));
}
__device__ __forceinline__ float ex2f(float x) {
    float y; asm("ex2.approx.f32 %0, %1;" : "=f"(y) : "f"(x)); return y;
}
__device__ __forceinline__ uint32_t pack_bf2(float x, float y) {
    uint32_t d; asm("cvt.rn.bf16x2.f32 %0, %1, %2;" : "=r"(d) : "f"(y), "f"(x)); return d;
}
__device__ __forceinline__ void split2(float x, float y, uint32_t& hi, uint32_t& lo) {
    hi = pack_bf2(x, y);
    float hx = __uint_as_float(hi << 16);
    float hy = __uint_as_float(hi & 0xffff0000u);
    lo = pack_bf2(x - hx, y - hy);
}
__device__ __forceinline__ void cp_async16(uint32_t saddr, const void* g) {
    asm volatile("cp.async.cg.shared.global [%0], [%1], 16;" :: "r"(saddr), "l"(g) : "memory");
}

// ============================================================================
// split fp32 -> bf16 hi/lo
// ============================================================================
__global__ __launch_bounds__(256) void split_kernel(
    const float* __restrict__ src, unsigned short* __restrict__ hi,
    unsigned short* __restrict__ lo, int n_valid, int n_total)
{
    int i = (blockIdx.x * 256 + threadIdx.x) * 2;
    if (i >= n_total) return;
    float2 v = (i < n_valid) ? *(const float2*)(src + i) : make_float2(0.f, 0.f);
    uint32_t h, l;
    split2(v.x, v.y, h, l);
    *(unsigned int*)(hi + i) = h;
    *(unsigned int*)(lo + i) = l;
}

// ============================================================================
// mma.sync bf16x3 GEMM (unchanged from R4)
// ============================================================================
#define SM_AH  0
#define SM_AL  16384
#define SM_BH  32768
#define SM_BL  49152
#define GEMM_SMEM 65536
#define NCHUNK (DIMN / 64)

__global__ __launch_bounds__(256, 2) void gemm_tc(
    const unsigned short* __restrict__ Ahi, const unsigned short* __restrict__ Alo,
    const unsigned short* __restrict__ Bhi, const unsigned short* __restrict__ Blo,
    const float* __restrict__ bias, float* __restrict__ C,
    unsigned short* __restrict__ Chi, unsigned short* __restrict__ Clo, int Mvalid)
{
    extern __shared__ __align__(1024) char smem[];
    const uint32_t sb = smem_to_u32(smem);
    const int tid  = threadIdx.x;
    const int lane = tid & 31;
    const int wid  = tid >> 5;
    const int wm   = wid & 1;
    const int wn   = wid >> 1;
    const int bm = blockIdx.y * 128;
    const int bn = blockIdx.x * 128;

    const int r0 = tid >> 3;
    const int c8 = tid & 7;
    const uint32_t st_off = SWZ128((uint32_t)(r0 * 128 + c8 * 16));

    uint32_t aoff[4], akey[4];
#pragma unroll
    for (int mf = 0; mf < 4; ++mf) {
        int arow = wm * 64 + mf * 16 + (lane & 15);
        aoff[mf] = (uint32_t)(arow * 128);
        akey[mf] = (uint32_t)((arow & 7) << 4);
    }
    uint32_t boff[4], bkey[4];
    {
        int l = lane & 15;
#pragma unroll
        for (int nf = 0; nf < 4; ++nf) {
            int brow = wn * 32 + nf * 8 + (l & 7);
            boff[nf] = (uint32_t)(brow * 128);
            bkey[nf] = (uint32_t)((brow & 7) << 4);
        }
    }
    const uint32_t abit = (uint32_t)((lane >> 4) << 4);
    const uint32_t bbit = (uint32_t)((((lane & 15) >> 3) & 1) << 4);

    float acc[4][4][4];
#pragma unroll
    for (int mf = 0; mf < 4; ++mf)
#pragma unroll
        for (int nf = 0; nf < 4; ++nf)
#pragma unroll
            for (int e = 0; e < 4; ++e) acc[mf][nf][e] = 0.f;

    for (int chunk = 0; chunk < NCHUNK; ++chunk) {
        const int k0 = chunk * 64;
        __syncthreads();
        {
            const unsigned short* srcs[4] = {Ahi, Alo, Bhi, Blo};
            const int rowbase[4] = {bm, bm, bn, bn};
            const uint32_t dsts[4] = {SM_AH, SM_AL, SM_BH, SM_BL};
#pragma unroll
            for (int t = 0; t < 4; ++t) {
                const unsigned short* s = srcs[t] + (size_t)(rowbase[t] + r0) * DIMN + k0 + c8 * 8;
                char* d = smem + dsts[t] + st_off;
#pragma unroll
                for (int i = 0; i < 4; ++i)
                    *(uint4*)(d + i * 4096) = *(const uint4*)(s + (size_t)(i * 32) * DIMN);
            }
        }
        __syncthreads();

#pragma unroll
        for (int ks = 0; ks < 4; ++ks) {
            const uint32_t kb = (uint32_t)(ks * 32);
            uint32_t bh[4][2], bl[4][2];
#pragma unroll
            for (int nf = 0; nf < 4; ++nf) {
                uint32_t ad = sb + SM_BH + boff[nf] + ((kb + bbit) ^ bkey[nf]);
                ldsm_x2(bh[nf], ad);
                ldsm_x2(bl[nf], ad + (SM_BL - SM_BH));
            }
#pragma unroll
            for (int mf = 0; mf < 4; ++mf) {
                uint32_t ah[4], al[4];
                uint32_t ad = sb + SM_AH + aoff[mf] + ((kb + abit) ^ akey[mf]);
                ldsm_x4(ah, ad);
                ldsm_x4(al, ad + (SM_AL - SM_AH));
#pragma unroll
                for (int nf = 0; nf < 4; ++nf) {
                    mma_bf16(acc[mf][nf], ah, bh[nf]);
                    mma_bf16(acc[mf][nf], ah, bl[nf]);
                    mma_bf16(acc[mf][nf], al, bh[nf]);
                }
            }
        }
    }

    const int row0 = bm + wm * 64 + (lane >> 2);
    const int col0 = bn + wn * 32 + (lane & 3) * 2;
#pragma unroll
    for (int nf = 0; nf < 4; ++nf) {
        const int c = col0 + nf * 8;
        const float2 bb = *(const float2*)(bias + c);
#pragma unroll
        for (int mf = 0; mf < 4; ++mf) {
            const int r = row0 + mf * 16;
            if (Chi) {
                uint32_t h, l;
                if (r < Mvalid) {
                    split2(acc[mf][nf][0] + bb.x, acc[mf][nf][1] + bb.y, h, l);
                    *(unsigned int*)(Chi + (size_t)r * DIMN + c) = h;
                    *(unsigned int*)(Clo + (size_t)r * DIMN + c) = l;
                }
                if (r + 8 < Mvalid) {
                    split2(acc[mf][nf][2] + bb.x, acc[mf][nf][3] + bb.y, h, l);
                    *(unsigned int*)(Chi + (size_t)(r + 8) * DIMN + c) = h;
                    *(unsigned int*)(Clo + (size_t)(r + 8) * DIMN + c) = l;
                }
            } else {
                if (r < Mvalid) {
                    float2 v; v.x = acc[mf][nf][0] + bb.x; v.y = acc[mf][nf][1] + bb.y;
                    *(float2*)(C + (size_t)r * DIMN + c) = v;
                }
                if (r + 8 < Mvalid) {
                    float2 v; v.x = acc[mf][nf][2] + bb.x; v.y = acc[mf][nf][3] + bb.y;
                    *(float2*)(C + (size_t)(r + 8) * DIMN + c) = v;
                }
            }
        }
    }
}

// ============================================================================
// Fused RMSNorm + 3D RoPE (unchanged)
// ============================================================================
__global__ __launch_bounds__(256) void rmsrope_kernel(
    const float* __restrict__ Qm, const float* __restrict__ Km,
    const float* __restrict__ gq, const float* __restrict__ gk,
    const float* __restrict__ cf, const float* __restrict__ sf,
    const float* __restrict__ ch, const float* __restrict__ sh,
    const float* __restrict__ cw, const float* __restrict__ sw,
    unsigned short* __restrict__ qh, unsigned short* __restrict__ ql,
    unsigned short* __restrict__ kh, unsigned short* __restrict__ kl)
{
    const int s = blockIdx.x;
    const int tid = threadIdx.x;
    const int f  = s / (HHG * WWG);
    const int rm = s - f * (HHG * WWG);
    const int hh = rm / WWG;
    const int ww = rm - hh * WWG;

    float co[3], si[3];
#pragma unroll
    for (int p = 0; p < 3; ++p) {
        int c = (tid * 3 + p) & 63;
        if (c < CF)            { co[p] = cf[f  * CF  + c];              si[p] = sf[f  * CF  + c]; }
        else if (c < CF + CHH) { co[p] = ch[hh * CHH + (c - CF)];       si[p] = sh[hh * CHH + (c - CF)]; }
        else                   { co[p] = cw[ww * CWW + (c - CF - CHH)]; si[p] = sw[ww * CWW + (c - CF - CHH)]; }
    }

    __shared__ float red[8];
    __shared__ float bcast;

    for (int which = 0; which < 2; ++which) {
        const float* T = which ? Km : Qm;
        const float* g = which ? gk : gq;
        unsigned short* oh = which ? kh : qh;
        unsigned short* ol = which ? kl : ql;
        const float post = which ? 1.0f : QK_SCALE_LOG2E;
        const size_t base = (size_t)s * DIMN + tid * 6;

        float v[6];
#pragma unroll
        for (int p = 0; p < 3; ++p) {
            float2 t = *(const float2*)(T + base + 2 * p);
            v[2 * p] = t.x; v[2 * p + 1] = t.y;
        }
        float ss = 0.f;
#pragma unroll
        for (int e = 0; e < 6; ++e) ss += v[e] * v[e];
        for (int off = 16; off; off >>= 1) ss += __shfl_xor_sync(0xffffffffu, ss, off);
        if ((tid & 31) == 0) red[tid >> 5] = ss;
        __syncthreads();
        if (tid < 32) {
            float t = (tid < 8) ? red[tid] : 0.f;
            for (int off = 4; off; off >>= 1) t += __shfl_xor_sync(0xffffffffu, t, off);
            if (tid == 0) bcast = t;
        }
        __syncthreads();
        const float rinv = rsqrtf(bcast * (1.0f / DIMN) + 1e-6f);

#pragma unroll
        for (int p = 0; p < 3; ++p) {
            float e = v[2 * p]     * rinv * g[tid * 6 + 2 * p];
            float o = v[2 * p + 1] * rinv * g[tid * 6 + 2 * p + 1];
            float rx = (e * co[p] - o * si[p]) * post;
            float ry = (e * si[p] + o * co[p]) * post;
            uint32_t hw, lw;
            split2(rx, ry, hw, lw);
            *(unsigned int*)(oh + base + 2 * p) = hw;
            *(unsigned int*)(ol + base + 2 * p) = lw;
        }
        __syncthreads();
    }
}

// ============================================================================
// Flash attention, HMMA bf16x3. 256 threads, 2 CTAs/SM (4 warps/SMSP).
// BQ=64, BK=32. 8 warps = 4 q-tiles(16 rows) x 2 key-halves(16 of 32 keys).
// Q hi/lo resident in smem (32KB); K/V hi/lo double-buffered (2x32KB).
// Per-warp online softmax over its key subset; pairwise m/l/O merge at end.
// ============================================================================
#define F2_QH   0
#define F2_QL   16384
#define F2_ST0  32768
#define F2_KH   0
#define F2_KL   8192
#define F2_VH   16384
#define F2_VL   24576
#define F2_ML   98304
#define FLASH2_SMEM (98304 + 2048)
#define NKT2 (S_LEN / 32)   // 126

__global__ __launch_bounds__(256, 2) void flash_tc2(
    const unsigned short* __restrict__ qh_, const unsigned short* __restrict__ ql_,
    const unsigned short* __restrict__ kh_, const unsigned short* __restrict__ kl_,
    const unsigned short* __restrict__ vh_, const unsigned short* __restrict__ vl_,
    unsigned short* __restrict__ oh_, unsigned short* __restrict__ ol_)
{
    extern __shared__ __align__(1024) char sm[];
    const uint32_t sb = smem_to_u32(sm);
    const int tid = threadIdx.x;
    const int lane = tid & 31;
    const int w = tid >> 5;         // 0..7
    const int nh = w & 1;           // key-half
    const int qm = w >> 1;          // q-tile 0..3
    const int l15 = lane & 15;
    const int h = blockIdx.y;
    const int q0 = blockIdx.x * 64;

    // ---- stage Q (hi/lo) resident: 64 rows x 128 cols, 2 chunks of [64][64c] ----
    {
        const unsigned short* srcs[2] = {qh_, ql_};
#pragma unroll
        for (int hl = 0; hl < 2; ++hl) {
            const unsigned short* s = srcs[hl];
#pragma unroll
            for (int i = 0; i < 4; ++i) {
                int idx = tid + i * 256;
                int qr = idx >> 4, c16 = idx & 15;
                uint4 v = *(const uint4*)(s + (size_t)(q0 + qr) * DIMN + h * HD + c16 * 8);
                uint32_t off = (uint32_t)(hl * 16384 + (c16 >> 3) * 8192)
                             + SWZ128((uint32_t)(qr * 128 + (c16 & 7) * 16));
                *(uint4*)(sm + off) = v;
            }
        }
    }

    // ---- K/V stage loader: 4 tiles x [32 rows][128 cols], 2 chunks of 4KB ----
    const int srow = tid >> 3;      // 0..31
    const int sc8 = tid & 7;
    const uint32_t so0 = SWZ128((uint32_t)(srow * 128 + sc8 * 16));
    auto issue_stage = [&](int kt, int st) {
        const int key0 = kt * 32;
        const unsigned short* srcs[4] = {kh_, kl_, vh_, vl_};
        uint32_t base = sb + (uint32_t)(F2_ST0 + st * 32768);
#pragma unroll
        for (int t = 0; t < 4; ++t) {
            const unsigned short* sp = srcs[t] + (size_t)(key0 + srow) * DIMN + h * HD;
            cp_async16(base + (uint32_t)(t * 8192) + so0, sp + sc8 * 8);
            cp_async16(base + (uint32_t)(t * 8192 + 4096) + so0, sp + (sc8 + 8) * 8);
        }
        asm volatile("cp.async.commit_group;" ::: "memory");
    };

    float oacc[16][4];
#pragma unroll
    for (int nt = 0; nt < 16; ++nt)
#pragma unroll
        for (int e = 0; e < 4; ++e) oacc[nt][e] = 0.f;
    float mrow0 = -1e30f, mrow1 = -1e30f, lrow0 = 0.f, lrow1 = 0.f;

    // Q addressing
    const int qrow = qm * 16 + l15;
    const uint32_t qrowb = (uint32_t)(qrow * 128);
    const uint32_t qc8sel = (uint32_t)(lane >> 4);

    issue_stage(0, 0);

    for (int kt = 0; kt < NKT2; ++kt) {
        const int st = kt & 1;
        if (kt < NKT2 - 1) {
            issue_stage(kt + 1, st ^ 1);
            asm volatile("cp.async.wait_group 1;" ::: "memory");
        } else {
            asm volatile("cp.async.wait_group 0;" ::: "memory");
        }
        __syncthreads();

        const uint32_t stb = sb + (uint32_t)(F2_ST0 + st * 32768);

        // ---- scores: 16 q-rows x 16 k-cols (this warp's half) ----
        float sc[2][4];
        sc[0][0] = sc[0][1] = sc[0][2] = sc[0][3] = 0.f;
        sc[1][0] = sc[1][1] = sc[1][2] = sc[1][3] = 0.f;

#pragma unroll
        for (int ks = 0; ks < 8; ++ks) {
            const uint32_t qaddr = sb + (uint32_t)((ks >> 2) * 8192)
                + SWZ128(qrowb + (uint32_t)(((ks & 3) * 2 + qc8sel) * 16));
            uint32_t qh4[4], ql4[4];
            ldsm_x4(qh4, qaddr);
            ldsm_x4(ql4, qaddr + F2_QL);
            const uint32_t kchunk = (uint32_t)((ks >> 2) * 4096);
            const uint32_t kc8 = (uint32_t)(((ks & 3) * 2 + ((l15 >> 3) & 1)) * 16);
#pragma unroll
            for (int nt = 0; nt < 2; ++nt) {
                const uint32_t krow = (uint32_t)((nh * 16 + nt * 8 + (l15 & 7)) * 128);
                uint32_t addr = stb + F2_KH + kchunk + SWZ128(krow + kc8);
                uint32_t bh[2], bl[2];
                ldsm_x2(bh, addr);
                ldsm_x2(bl, addr + (F2_KL - F2_KH));
                mma_bf16(sc[nt], qh4, bh);
                mma_bf16(sc[nt], qh4, bl);
                mma_bf16(sc[nt], ql4, bh);
            }
        }

        // ---- online softmax (log2 units), per-warp key subset ----
        float mx0 = fmaxf(fmaxf(sc[0][0], sc[0][1]), fmaxf(sc[1][0], sc[1][1]));
        float mx1 = fmaxf(fmaxf(sc[0][2], sc[0][3]), fmaxf(sc[1][2], sc[1][3]));
        mx0 = fmaxf(mx0, __shfl_xor_sync(0xffffffffu, mx0, 1));
        mx0 = fmaxf(mx0, __shfl_xor_sync(0xffffffffu, mx0, 2));
        mx1 = fmaxf(mx1, __shfl_xor_sync(0xffffffffu, mx1, 1));
        mx1 = fmaxf(mx1, __shfl_xor_sync(0xffffffffu, mx1, 2));
        const float mn0 = fmaxf(mrow0, mx0);
        const float mn1 = fmaxf(mrow1, mx1);
        const float al0 = ex2f(mrow0 - mn0);
        const float al1 = ex2f(mrow1 - mn1);
        mrow0 = mn0; mrow1 = mn1;
        float rs0 = 0.f, rs1 = 0.f;
#pragma unroll
        for (int nt = 0; nt < 2; ++nt) {
            sc[nt][0] = ex2f(sc[nt][0] - mn0); rs0 += sc[nt][0];
            sc[nt][1] = ex2f(sc[nt][1] - mn0); rs0 += sc[nt][1];
            sc[nt][2] = ex2f(sc[nt][2] - mn1); rs1 += sc[nt][2];
            sc[nt][3] = ex2f(sc[nt][3] - mn1); rs1 += sc[nt][3];
        }
        rs0 += __shfl_xor_sync(0xffffffffu, rs0, 1);
        rs0 += __shfl_xor_sync(0xffffffffu, rs0, 2);
        rs1 += __shfl_xor_sync(0xffffffffu, rs1, 1);
        rs1 += __shfl_xor_sync(0xffffffffu, rs1, 2);
        lrow0 = lrow0 * al0 + rs0;
        lrow1 = lrow1 * al1 + rs1;
        if (al0 != 1.0f || al1 != 1.0f) {
#pragma unroll
            for (int nt = 0; nt < 16; ++nt) {
                oacc[nt][0] *= al0; oacc[nt][1] *= al0;
                oacc[nt][2] *= al1; oacc[nt][3] *= al1;
            }
        }

        // ---- pack P (16x16) into one A-frag group (hi/lo) ----
        uint32_t pah[4], pal[4];
        split2(sc[0][0], sc[0][1], pah[0], pal[0]);
        split2(sc[0][2], sc[0][3], pah[1], pal[1]);
        split2(sc[1][0], sc[1][1], pah[2], pal[2]);
        split2(sc[1][2], sc[1][3], pah[3], pal[3]);

        // ---- O += P @ V (this warp's 16 keys) ----
        const uint32_t vrow = (uint32_t)((nh * 16 + ((l15 >> 3) & 1) * 8 + (l15 & 7)) * 128);
#pragma unroll
        for (int nt = 0; nt < 16; ++nt) {
            uint32_t addr = stb + F2_VH + (uint32_t)((nt >> 3) * 4096)
                          + SWZ128(vrow + (uint32_t)((nt & 7) * 16));
            uint32_t bh[2], bl[2];
            ldsm_x2_t(bh, addr);
            ldsm_x2_t(bl, addr + (F2_VL - F2_VH));
            mma_bf16(oacc[nt], pah, bh);
            mma_bf16(oacc[nt], pah, bl);
            mma_bf16(oacc[nt], pal, bh);
        }
        __syncthreads();
    }

    // ---- merge key-half pairs: nh=1 publishes, nh=0 merges & writes ----
    __syncthreads();
    if (nh == 1) {
        float* dst = (float*)(sm + F2_ST0) + qm * 2048 + lane * 64;
#pragma unroll
        for (int nt = 0; nt < 16; ++nt) {
            dst[nt * 4 + 0] = oacc[nt][0];
            dst[nt * 4 + 1] = oacc[nt][1];
            dst[nt * 4 + 2] = oacc[nt][2];
            dst[nt * 4 + 3] = oacc[nt][3];
        }
        float* ml = (float*)(sm + F2_ML) + qm * 128 + lane * 4;
        ml[0] = mrow0; ml[1] = lrow0; ml[2] = mrow1; ml[3] = lrow1;
    }
    __syncthreads();
    if (nh == 0) {
        const float* src = (const float*)(sm + F2_ST0) + qm * 2048 + lane * 64;
        const float* ml = (const float*)(sm + F2_ML) + qm * 128 + lane * 4;
        const float m1 = ml[0], l1 = ml[1], m1b = ml[2], l1b = ml[3];
        const float M0 = fmaxf(mrow0, m1);
        const float M1 = fmaxf(mrow1, m1b);
        const float a0 = ex2f(mrow0 - M0), b0 = ex2f(m1 - M0);
        const float a1 = ex2f(mrow1 - M1), b1 = ex2f(m1b - M1);
        const float inv0 = 1.0f / (lrow0 * a0 + l1 * b0);
        const float inv1 = 1.0f / (lrow1 * a1 + l1b * b1);

        const int r0 = q0 + qm * 16 + (lane >> 2);
        const int cbase = h * HD + (lane & 3) * 2;
#pragma unroll
        for (int nt = 0; nt < 16; ++nt) {
            const int c = cbase + nt * 8;
            float v0 = (oacc[nt][0] * a0 + src[nt * 4 + 0] * b0) * inv0;
            float v1 = (oacc[nt][1] * a0 + src[nt * 4 + 1] * b0) * inv0;
            float v2 = (oacc[nt][2] * a1 + src[nt * 4 + 2] * b1) * inv1;
            float v3 = (oacc[nt][3] * a1 + src[nt * 4 + 3] * b1) * inv1;
            uint32_t hw, lw;
            split2(v0, v1, hw, lw);
            *(unsigned int*)(oh_ + (size_t)r0 * DIMN + c) = hw;
            *(unsigned int*)(ol_ + (size_t)r0 * DIMN + c) = lw;
            split2(v2, v3, hw, lw);
            *(unsigned int*)(oh_ + (size_t)(r0 + 8) * DIMN + c) = hw;
            *(unsigned int*)(ol_ + (size_t)(r0 + 8) * DIMN + c) = lw;
        }
    }
}

// ============================================================================
// launch
// ============================================================================
extern "C" void kernel_launch(void* const* d_in, const int* in_sizes, int n_in,
                              void* d_out, int out_size)
{
    const float* x  = (const float*)d_in[0];
    const float* Wq = (const float*)d_in[1];
    const float* bq = (const float*)d_in[2];
    const float* Wk = (const float*)d_in[3];
    const float* bk = (const float*)d_in[4];
    const float* Wv = (const float*)d_in[5];
    const float* bv = (const float*)d_in[6];
    const float* Wo = (const float*)d_in[7];
    const float* bo = (const float*)d_in[8];
    const float* gq = (const float*)d_in[9];
    const float* gk = (const float*)d_in[10];
    const float* cf = (const float*)d_in[11];
    const float* sf = (const float*)d_in[12];
    const float* ch = (const float*)d_in[13];
    const float* sh = (const float*)d_in[14];
    const float* cw = (const float*)d_in[15];
    const float* sw = (const float*)d_in[16];
    float* out = (float*)d_out;

    float *Qd, *Kd;
    unsigned short *qh, *ql, *kh, *kl, *vh, *vl, *oh, *ol, *xh, *xl;
    unsigned short *wqh, *wql, *wkh, *wkl, *wvh, *wvl, *woh, *wol;
    cudaGetSymbolAddress((void**)&Qd, g_Q);
    cudaGetSymbolAddress((void**)&Kd, g_K);
    cudaGetSymbolAddress((void**)&qh, g_qh);  cudaGetSymbolAddress((void**)&ql, g_ql);
    cudaGetSymbolAddress((void**)&kh, g_kh);  cudaGetSymbolAddress((void**)&kl, g_kl);
    cudaGetSymbolAddress((void**)&vh, g_vh);  cudaGetSymbolAddress((void**)&vl, g_vl);
    cudaGetSymbolAddress((void**)&oh, g_oh);  cudaGetSymbolAddress((void**)&ol, g_ol);
    cudaGetSymbolAddress((void**)&xh, g_xh);  cudaGetSymbolAddress((void**)&xl, g_xl);
    cudaGetSymbolAddress((void**)&wqh, g_wqh); cudaGetSymbolAddress((void**)&wql, g_wql);
    cudaGetSymbolAddress((void**)&wkh, g_wkh); cudaGetSymbolAddress((void**)&wkl, g_wkl);
    cudaGetSymbolAddress((void**)&wvh, g_wvh); cudaGetSymbolAddress((void**)&wvl, g_wvl);
    cudaGetSymbolAddress((void**)&woh, g_woh); cudaGetSymbolAddress((void**)&wol, g_wol);

    cudaFuncSetAttribute(gemm_tc,
                         cudaFuncAttributeMaxDynamicSharedMemorySize, GEMM_SMEM);
    cudaFuncSetAttribute(flash_tc2,
                         cudaFuncAttributeMaxDynamicSharedMemorySize, FLASH2_SMEM);

    const int NW = DIMN * DIMN;
    const int NXV = S_LEN * DIMN;
    const int NXT = S_PAD * DIMN;

    split_kernel<<<NXT / 512, 256>>>(x, xh, xl, NXV, NXT);
    split_kernel<<<NW / 512, 256>>>(Wq, wqh, wql, NW, NW);
    split_kernel<<<NW / 512, 256>>>(Wk, wkh, wkl, NW, NW);
    split_kernel<<<NW / 512, 256>>>(Wv, wvh, wvl, NW, NW);
    split_kernel<<<NW / 512, 256>>>(Wo, woh, wol, NW, NW);

    dim3 ggrid(DIMN / 128, S_PAD / 128);
    gemm_tc<<<ggrid, 256, GEMM_SMEM>>>(xh, xl, wqh, wql, bq, Qd, nullptr, nullptr, S_PAD);
    gemm_tc<<<ggrid, 256, GEMM_SMEM>>>(xh, xl, wkh, wkl, bk, Kd, nullptr, nullptr, S_PAD);
    gemm_tc<<<ggrid, 256, GEMM_SMEM>>>(xh, xl, wvh, wvl, bv, nullptr, vh, vl, S_PAD);

    rmsrope_kernel<<<S_LEN, 256>>>(Qd, Kd, gq, gk, cf, sf, ch, sh, cw, sw,
                                   qh, ql, kh, kl);

    flash_tc2<<<dim3(S_LEN / 64, NHEAD), 256, FLASH2_SMEM>>>(qh, ql, kh, kl, vh, vl, oh, ol);

    gemm_tc<<<ggrid, 256, GEMM_SMEM>>>(oh, ol, woh, wol, bo, out, nullptr, nullptr, S_LEN);
}

// round 14
// speedup vs baseline: 1.0050x; 1.0047x over previous
#include <cuda_runtime.h>
#include <cuda_bf16.h>
#include <cstdint>
#include <math.h>

// ---------------- problem constants ----------------
#define S_LEN 4032
#define S_PAD 4096
#define DIMN  1536
#define NHEAD 12
#define HD    128
#define FF    9
#define HHG   16
#define WWG   28
#define CF    22
#define CHH   21
#define CWW   21

#define QK_SCALE_LOG2E ((float)(1.4426950408889634 * 0.08838834764831845))

// ---------------- scratch ----------------
__device__ float g_Q[S_PAD * DIMN];
__device__ float g_K[S_PAD * DIMN];
__device__ unsigned short g_qh[S_PAD * DIMN], g_ql[S_PAD * DIMN];
__device__ unsigned short g_kh[S_PAD * DIMN], g_kl[S_PAD * DIMN];
__device__ unsigned short g_vh[S_PAD * DIMN], g_vl[S_PAD * DIMN];
__device__ unsigned short g_oh[S_PAD * DIMN], g_ol[S_PAD * DIMN];
__device__ unsigned short g_xh[S_PAD * DIMN], g_xl[S_PAD * DIMN];
__device__ unsigned short g_wqh[DIMN * DIMN], g_wql[DIMN * DIMN];
__device__ unsigned short g_wkh[DIMN * DIMN], g_wkl[DIMN * DIMN];
__device__ unsigned short g_wvh[DIMN * DIMN], g_wvl[DIMN * DIMN];
__device__ unsigned short g_woh[DIMN * DIMN], g_wol[DIMN * DIMN];

// ---------------- helpers ----------------
__device__ __forceinline__ uint32_t smem_to_u32(const void* p) {
    uint32_t a;
    asm("{ .reg .u64 t; cvta.to.shared.u64 t, %1; cvt.u32.u64 %0, t; }" : "=r"(a) : "l"(p));
    return a;
}
#define SWZ128(off) ((off) ^ (((off) >> 3) & 0x70))

__device__ __forceinline__ void ldsm_x4(uint32_t* r, uint32_t addr) {
    asm volatile("ldmatrix.sync.aligned.m8n8.x4.shared.b16 {%0,%1,%2,%3}, [%4];"
                 : "=r"(r[0]), "=r"(r[1]), "=r"(r[2]), "=r"(r[3]) : "r"(addr));
}
__device__ __forceinline__ void ldsm_x2(uint32_t* r, uint32_t addr) {
    asm volatile("ldmatrix.sync.aligned.m8n8.x2.shared.b16 {%0,%1}, [%2];"
                 : "=r"(r[0]), "=r"(r[1]) : "r"(addr));
}
__device__ __forceinline__ void ldsm_x2_t(uint32_t* r, uint32_t addr) {
    asm volatile("ldmatrix.sync.aligned.m8n8.x2.trans.shared.b16 {%0,%1}, [%2];"
                 : "=r"(r[0]), "=r"(r[1]) : "r"(addr));
}
__device__ __forceinline__ void mma_bf16(float* c, const uint32_t* a, const uint32_t* b) {
    asm volatile("mma.sync.aligned.m16n8k16.row.col.f32.bf16.bf16.f32 "
                 "{%0,%1,%2,%3}, {%4,%5,%6,%7}, {%8,%9}, {%0,%1,%2,%3};"
                 : "+f"(c[0]), "+f"(c[1]), "+f"(c[2]), "+f"(c[3])
                 : "r"(a[0]), "r"(a[1]), "r"(a[2]), "r"(a[3]), "r"(b[0]), "r"(b[1]));
}
__device__ __forceinline__ float ex2f(float x) {
    float y; asm("ex2.approx.f32 %0, %1;" : "=f"(y) : "f"(x)); return y;
}
__device__ __forceinline__ uint32_t pack_bf2(float x, float y) {
    uint32_t d; asm("cvt.rn.bf16x2.f32 %0, %1, %2;" : "=r"(d) : "f"(y), "f"(x)); return d;
}
__device__ __forceinline__ void split2(float x, float y, uint32_t& hi, uint32_t& lo) {
    hi = pack_bf2(x, y);
    float hx = __uint_as_float(hi << 16);
    float hy = __uint_as_float(hi & 0xffff0000u);
    lo = pack_bf2(x - hx, y - hy);
}
__device__ __forceinline__ void cp_async16(uint32_t saddr, const void* g) {
    asm volatile("cp.async.cg.shared.global [%0], [%1], 16;" :: "r"(saddr), "l"(g) : "memory");
}

// ============================================================================
// split fp32 -> bf16 hi/lo
// ============================================================================
__global__ __launch_bounds__(256) void split_kernel(
    const float* __restrict__ src, unsigned short* __restrict__ hi,
    unsigned short* __restrict__ lo, int n_valid, int n_total)
{
    int i = (blockIdx.x * 256 + threadIdx.x) * 2;
    if (i >= n_total) return;
    float2 v = (i < n_valid) ? *(const float2*)(src + i) : make_float2(0.f, 0.f);
    uint32_t h, l;
    split2(v.x, v.y, h, l);
    *(unsigned int*)(hi + i) = h;
    *(unsigned int*)(lo + i) = l;
}

// ============================================================================
// mma.sync bf16x3 GEMM (unchanged from R4)
// ============================================================================
#define SM_AH  0
#define SM_AL  16384
#define SM_BH  32768
#define SM_BL  49152
#define GEMM_SMEM 65536
#define NCHUNK (DIMN / 64)

__global__ __launch_bounds__(256, 2) void gemm_tc(
    const unsigned short* __restrict__ Ahi, const unsigned short* __restrict__ Alo,
    const unsigned short* __restrict__ Bhi, const unsigned short* __restrict__ Blo,
    const float* __restrict__ bias, float* __restrict__ C,
    unsigned short* __restrict__ Chi, unsigned short* __restrict__ Clo, int Mvalid)
{
    extern __shared__ __align__(1024) char smem[];
    const uint32_t sb = smem_to_u32(smem);
    const int tid  = threadIdx.x;
    const int lane = tid & 31;
    const int wid  = tid >> 5;
    const int wm   = wid & 1;
    const int wn   = wid >> 1;
    const int bm = blockIdx.y * 128;
    const int bn = blockIdx.x * 128;

    const int r0 = tid >> 3;
    const int c8 = tid & 7;
    const uint32_t st_off = SWZ128((uint32_t)(r0 * 128 + c8 * 16));

    uint32_t aoff[4], akey[4];
#pragma unroll
    for (int mf = 0; mf < 4; ++mf) {
        int arow = wm * 64 + mf * 16 + (lane & 15);
        aoff[mf] = (uint32_t)(arow * 128);
        akey[mf] = (uint32_t)((arow & 7) << 4);
    }
    uint32_t boff[4], bkey[4];
    {
        int l = lane & 15;
#pragma unroll
        for (int nf = 0; nf < 4; ++nf) {
            int brow = wn * 32 + nf * 8 + (l & 7);
            boff[nf] = (uint32_t)(brow * 128);
            bkey[nf] = (uint32_t)((brow & 7) << 4);
        }
    }
    const uint32_t abit = (uint32_t)((lane >> 4) << 4);
    const uint32_t bbit = (uint32_t)((((lane & 15) >> 3) & 1) << 4);

    float acc[4][4][4];
#pragma unroll
    for (int mf = 0; mf < 4; ++mf)
#pragma unroll
        for (int nf = 0; nf < 4; ++nf)
#pragma unroll
            for (int e = 0; e < 4; ++e) acc[mf][nf][e] = 0.f;

    for (int chunk = 0; chunk < NCHUNK; ++chunk) {
        const int k0 = chunk * 64;
        __syncthreads();
        {
            const unsigned short* srcs[4] = {Ahi, Alo, Bhi, Blo};
            const int rowbase[4] = {bm, bm, bn, bn};
            const uint32_t dsts[4] = {SM_AH, SM_AL, SM_BH, SM_BL};
#pragma unroll
            for (int t = 0; t < 4; ++t) {
                const unsigned short* s = srcs[t] + (size_t)(rowbase[t] + r0) * DIMN + k0 + c8 * 8;
                char* d = smem + dsts[t] + st_off;
#pragma unroll
                for (int i = 0; i < 4; ++i)
                    *(uint4*)(d + i * 4096) = *(const uint4*)(s + (size_t)(i * 32) * DIMN);
            }
        }
        __syncthreads();

#pragma unroll
        for (int ks = 0; ks < 4; ++ks) {
            const uint32_t kb = (uint32_t)(ks * 32);
            uint32_t bh[4][2], bl[4][2];
#pragma unroll
            for (int nf = 0; nf < 4; ++nf) {
                uint32_t ad = sb + SM_BH + boff[nf] + ((kb + bbit) ^ bkey[nf]);
                ldsm_x2(bh[nf], ad);
                ldsm_x2(bl[nf], ad + (SM_BL - SM_BH));
            }
#pragma unroll
            for (int mf = 0; mf < 4; ++mf) {
                uint32_t ah[4], al[4];
                uint32_t ad = sb + SM_AH + aoff[mf] + ((kb + abit) ^ akey[mf]);
                ldsm_x4(ah, ad);
                ldsm_x4(al, ad + (SM_AL - SM_AH));
#pragma unroll
                for (int nf = 0; nf < 4; ++nf) {
                    mma_bf16(acc[mf][nf], ah, bh[nf]);
                    mma_bf16(acc[mf][nf], ah, bl[nf]);
                    mma_bf16(acc[mf][nf], al, bh[nf]);
                }
            }
        }
    }

    const int row0 = bm + wm * 64 + (lane >> 2);
    const int col0 = bn + wn * 32 + (lane & 3) * 2;
#pragma unroll
    for (int nf = 0; nf < 4; ++nf) {
        const int c = col0 + nf * 8;
        const float2 bb = *(const float2*)(bias + c);
#pragma unroll
        for (int mf = 0; mf < 4; ++mf) {
            const int r = row0 + mf * 16;
            if (Chi) {
                uint32_t h, l;
                if (r < Mvalid) {
                    split2(acc[mf][nf][0] + bb.x, acc[mf][nf][1] + bb.y, h, l);
                    *(unsigned int*)(Chi + (size_t)r * DIMN + c) = h;
                    *(unsigned int*)(Clo + (size_t)r * DIMN + c) = l;
                }
                if (r + 8 < Mvalid) {
                    split2(acc[mf][nf][2] + bb.x, acc[mf][nf][3] + bb.y, h, l);
                    *(unsigned int*)(Chi + (size_t)(r + 8) * DIMN + c) = h;
                    *(unsigned int*)(Clo + (size_t)(r + 8) * DIMN + c) = l;
                }
            } else {
                if (r < Mvalid) {
                    float2 v; v.x = acc[mf][nf][0] + bb.x; v.y = acc[mf][nf][1] + bb.y;
                    *(float2*)(C + (size_t)r * DIMN + c) = v;
                }
                if (r + 8 < Mvalid) {
                    float2 v; v.x = acc[mf][nf][2] + bb.x; v.y = acc[mf][nf][3] + bb.y;
                    *(float2*)(C + (size_t)(r + 8) * DIMN + c) = v;
                }
            }
        }
    }
}

// ============================================================================
// Fused RMSNorm + 3D RoPE (unchanged)
// ============================================================================
__global__ __launch_bounds__(256) void rmsrope_kernel(
    const float* __restrict__ Qm, const float* __restrict__ Km,
    const float* __restrict__ gq, const float* __restrict__ gk,
    const float* __restrict__ cf, const float* __restrict__ sf,
    const float* __restrict__ ch, const float* __restrict__ sh,
    const float* __restrict__ cw, const float* __restrict__ sw,
    unsigned short* __restrict__ qh, unsigned short* __restrict__ ql,
    unsigned short* __restrict__ kh, unsigned short* __restrict__ kl)
{
    const int s = blockIdx.x;
    const int tid = threadIdx.x;
    const int f  = s / (HHG * WWG);
    const int rm = s - f * (HHG * WWG);
    const int hh = rm / WWG;
    const int ww = rm - hh * WWG;

    float co[3], si[3];
#pragma unroll
    for (int p = 0; p < 3; ++p) {
        int c = (tid * 3 + p) & 63;
        if (c < CF)            { co[p] = cf[f  * CF  + c];              si[p] = sf[f  * CF  + c]; }
        else if (c < CF + CHH) { co[p] = ch[hh * CHH + (c - CF)];       si[p] = sh[hh * CHH + (c - CF)]; }
        else                   { co[p] = cw[ww * CWW + (c - CF - CHH)]; si[p] = sw[ww * CWW + (c - CF - CHH)]; }
    }

    __shared__ float red[8];
    __shared__ float bcast;

    for (int which = 0; which < 2; ++which) {
        const float* T = which ? Km : Qm;
        const float* g = which ? gk : gq;
        unsigned short* oh = which ? kh : qh;
        unsigned short* ol = which ? kl : ql;
        const float post = which ? 1.0f : QK_SCALE_LOG2E;
        const size_t base = (size_t)s * DIMN + tid * 6;

        float v[6];
#pragma unroll
        for (int p = 0; p < 3; ++p) {
            float2 t = *(const float2*)(T + base + 2 * p);
            v[2 * p] = t.x; v[2 * p + 1] = t.y;
        }
        float ss = 0.f;
#pragma unroll
        for (int e = 0; e < 6; ++e) ss += v[e] * v[e];
        for (int off = 16; off; off >>= 1) ss += __shfl_xor_sync(0xffffffffu, ss, off);
        if ((tid & 31) == 0) red[tid >> 5] = ss;
        __syncthreads();
        if (tid < 32) {
            float t = (tid < 8) ? red[tid] : 0.f;
            for (int off = 4; off; off >>= 1) t += __shfl_xor_sync(0xffffffffu, t, off);
            if (tid == 0) bcast = t;
        }
        __syncthreads();
        const float rinv = rsqrtf(bcast * (1.0f / DIMN) + 1e-6f);

#pragma unroll
        for (int p = 0; p < 3; ++p) {
            float e = v[2 * p]     * rinv * g[tid * 6 + 2 * p];
            float o = v[2 * p + 1] * rinv * g[tid * 6 + 2 * p + 1];
            float rx = (e * co[p] - o * si[p]) * post;
            float ry = (e * si[p] + o * co[p]) * post;
            uint32_t hw, lw;
            split2(rx, ry, hw, lw);
            *(unsigned int*)(oh + base + 2 * p) = hw;
            *(unsigned int*)(ol + base + 2 * p) = lw;
        }
        __syncthreads();
    }
}

// ============================================================================
// Flash attention, HMMA bf16x3. 256 threads, 2 CTAs/SM (4 warps/SMSP).
// BQ=64, BK=32. 8 warps = 4 q-tiles(16 rows) x 2 key-halves(16 of 32 keys).
// Q hi/lo resident in smem (32KB); K/V hi/lo double-buffered (2x32KB).
// Per-warp online softmax over its key subset; pairwise m/l/O merge at end.
// ============================================================================
#define F2_QH   0
#define F2_QL   16384
#define F2_ST0  32768
#define F2_KH   0
#define F2_KL   8192
#define F2_VH   16384
#define F2_VL   24576
#define F2_ML   98304
#define FLASH2_SMEM (98304 + 2048)
#define NKT2 (S_LEN / 32)   // 126

__global__ __launch_bounds__(256, 2) void flash_tc2(
    const unsigned short* __restrict__ qh_, const unsigned short* __restrict__ ql_,
    const unsigned short* __restrict__ kh_, const unsigned short* __restrict__ kl_,
    const unsigned short* __restrict__ vh_, const unsigned short* __restrict__ vl_,
    unsigned short* __restrict__ oh_, unsigned short* __restrict__ ol_)
{
    extern __shared__ __align__(1024) char sm[];
    const uint32_t sb = smem_to_u32(sm);
    const int tid = threadIdx.x;
    const int lane = tid & 31;
    const int w = tid >> 5;         // 0..7
    const int nh = w & 1;           // key-half
    const int qm = w >> 1;          // q-tile 0..3
    const int l15 = lane & 15;
    const int h = blockIdx.y;
    const int q0 = blockIdx.x * 64;

    // ---- stage Q (hi/lo) resident: 64 rows x 128 cols, 2 chunks of [64][64c] ----
    {
        const unsigned short* srcs[2] = {qh_, ql_};
#pragma unroll
        for (int hl = 0; hl < 2; ++hl) {
            const unsigned short* s = srcs[hl];
#pragma unroll
            for (int i = 0; i < 4; ++i) {
                int idx = tid + i * 256;
                int qr = idx >> 4, c16 = idx & 15;
                uint4 v = *(const uint4*)(s + (size_t)(q0 + qr) * DIMN + h * HD + c16 * 8);
                uint32_t off = (uint32_t)(hl * 16384 + (c16 >> 3) * 8192)
                             + SWZ128((uint32_t)(qr * 128 + (c16 & 7) * 16));
                *(uint4*)(sm + off) = v;
            }
        }
    }

    // ---- K/V stage loader: 4 tiles x [32 rows][128 cols], 2 chunks of 4KB ----
    const int srow = tid >> 3;      // 0..31
    const int sc8 = tid & 7;
    const uint32_t so0 = SWZ128((uint32_t)(srow * 128 + sc8 * 16));
    auto issue_stage = [&](int kt, int st) {
        const int key0 = kt * 32;
        const unsigned short* srcs[4] = {kh_, kl_, vh_, vl_};
        uint32_t base = sb + (uint32_t)(F2_ST0 + st * 32768);
#pragma unroll
        for (int t = 0; t < 4; ++t) {
            const unsigned short* sp = srcs[t] + (size_t)(key0 + srow) * DIMN + h * HD;
            cp_async16(base + (uint32_t)(t * 8192) + so0, sp + sc8 * 8);
            cp_async16(base + (uint32_t)(t * 8192 + 4096) + so0, sp + (sc8 + 8) * 8);
        }
        asm volatile("cp.async.commit_group;" ::: "memory");
    };

    float oacc[16][4];
#pragma unroll
    for (int nt = 0; nt < 16; ++nt)
#pragma unroll
        for (int e = 0; e < 4; ++e) oacc[nt][e] = 0.f;
    float mrow0 = -1e30f, mrow1 = -1e30f, lrow0 = 0.f, lrow1 = 0.f;

    // Q addressing
    const int qrow = qm * 16 + l15;
    const uint32_t qrowb = (uint32_t)(qrow * 128);
    const uint32_t qc8sel = (uint32_t)(lane >> 4);

    issue_stage(0, 0);

    for (int kt = 0; kt < NKT2; ++kt) {
        const int st = kt & 1;
        if (kt < NKT2 - 1) {
            issue_stage(kt + 1, st ^ 1);
            asm volatile("cp.async.wait_group 1;" ::: "memory");
        } else {
            asm volatile("cp.async.wait_group 0;" ::: "memory");
        }
        __syncthreads();

        const uint32_t stb = sb + (uint32_t)(F2_ST0 + st * 32768);

        // ---- scores: 16 q-rows x 16 k-cols (this warp's half) ----
        float sc[2][4];
        sc[0][0] = sc[0][1] = sc[0][2] = sc[0][3] = 0.f;
        sc[1][0] = sc[1][1] = sc[1][2] = sc[1][3] = 0.f;

#pragma unroll
        for (int ks = 0; ks < 8; ++ks) {
            const uint32_t qaddr = sb + (uint32_t)((ks >> 2) * 8192)
                + SWZ128(qrowb + (uint32_t)(((ks & 3) * 2 + qc8sel) * 16));
            uint32_t qh4[4], ql4[4];
            ldsm_x4(qh4, qaddr);
            ldsm_x4(ql4, qaddr + F2_QL);
            const uint32_t kchunk = (uint32_t)((ks >> 2) * 4096);
            const uint32_t kc8 = (uint32_t)(((ks & 3) * 2 + ((l15 >> 3) & 1)) * 16);
#pragma unroll
            for (int nt = 0; nt < 2; ++nt) {
                const uint32_t krow = (uint32_t)((nh * 16 + nt * 8 + (l15 & 7)) * 128);
                uint32_t addr = stb + F2_KH + kchunk + SWZ128(krow + kc8);
                uint32_t bh[2], bl[2];
                ldsm_x2(bh, addr);
                ldsm_x2(bl, addr + (F2_KL - F2_KH));
                mma_bf16(sc[nt], qh4, bh);
                mma_bf16(sc[nt], qh4, bl);
                mma_bf16(sc[nt], ql4, bh);
            }
        }

        // ---- online softmax (log2 units), per-warp key subset ----
        float mx0 = fmaxf(fmaxf(sc[0][0], sc[0][1]), fmaxf(sc[1][0], sc[1][1]));
        float mx1 = fmaxf(fmaxf(sc[0][2], sc[0][3]), fmaxf(sc[1][2], sc[1][3]));
        mx0 = fmaxf(mx0, __shfl_xor_sync(0xffffffffu, mx0, 1));
        mx0 = fmaxf(mx0, __shfl_xor_sync(0xffffffffu, mx0, 2));
        mx1 = fmaxf(mx1, __shfl_xor_sync(0xffffffffu, mx1, 1));
        mx1 = fmaxf(mx1, __shfl_xor_sync(0xffffffffu, mx1, 2));
        const float mn0 = fmaxf(mrow0, mx0);
        const float mn1 = fmaxf(mrow1, mx1);
        const float al0 = ex2f(mrow0 - mn0);
        const float al1 = ex2f(mrow1 - mn1);
        mrow0 = mn0; mrow1 = mn1;
        float rs0 = 0.f, rs1 = 0.f;
#pragma unroll
        for (int nt = 0; nt < 2; ++nt) {
            sc[nt][0] = ex2f(sc[nt][0] - mn0); rs0 += sc[nt][0];
            sc[nt][1] = ex2f(sc[nt][1] - mn0); rs0 += sc[nt][1];
            sc[nt][2] = ex2f(sc[nt][2] - mn1); rs1 += sc[nt][2];
            sc[nt][3] = ex2f(sc[nt][3] - mn1); rs1 += sc[nt][3];
        }
        rs0 += __shfl_xor_sync(0xffffffffu, rs0, 1);
        rs0 += __shfl_xor_sync(0xffffffffu, rs0, 2);
        rs1 += __shfl_xor_sync(0xffffffffu, rs1, 1);
        rs1 += __shfl_xor_sync(0xffffffffu, rs1, 2);
        lrow0 = lrow0 * al0 + rs0;
        lrow1 = lrow1 * al1 + rs1;
        if (al0 != 1.0f || al1 != 1.0f) {
#pragma unroll
            for (int nt = 0; nt < 16; ++nt) {
                oacc[nt][0] *= al0; oacc[nt][1] *= al0;
                oacc[nt][2] *= al1; oacc[nt][3] *= al1;
            }
        }

        // ---- pack P (16x16) into one A-frag group (hi/lo) ----
        uint32_t pah[4], pal[4];
        split2(sc[0][0], sc[0][1], pah[0], pal[0]);
        split2(sc[0][2], sc[0][3], pah[1], pal[1]);
        split2(sc[1][0], sc[1][1], pah[2], pal[2]);
        split2(sc[1][2], sc[1][3], pah[3], pal[3]);

        // ---- O += P @ V (this warp's 16 keys) ----
        const uint32_t vrow = (uint32_t)((nh * 16 + ((l15 >> 3) & 1) * 8 + (l15 & 7)) * 128);
#pragma unroll
        for (int nt = 0; nt < 16; ++nt) {
            uint32_t addr = stb + F2_VH + (uint32_t)((nt >> 3) * 4096)
                          + SWZ128(vrow + (uint32_t)((nt & 7) * 16));
            uint32_t bh[2], bl[2];
            ldsm_x2_t(bh, addr);
            ldsm_x2_t(bl, addr + (F2_VL - F2_VH));
            mma_bf16(oacc[nt], pah, bh);
            mma_bf16(oacc[nt], pah, bl);
            mma_bf16(oacc[nt], pal, bh);
        }
        __syncthreads();
    }

    // ---- merge key-half pairs: nh=1 publishes, nh=0 merges & writes ----
    __syncthreads();
    if (nh == 1) {
        float* dst = (float*)(sm + F2_ST0) + qm * 2048 + lane * 64;
#pragma unroll
        for (int nt = 0; nt < 16; ++nt) {
            dst[nt * 4 + 0] = oacc[nt][0];
            dst[nt * 4 + 1] = oacc[nt][1];
            dst[nt * 4 + 2] = oacc[nt][2];
            dst[nt * 4 + 3] = oacc[nt][3];
        }
        float* ml = (float*)(sm + F2_ML) + qm * 128 + lane * 4;
        ml[0] = mrow0; ml[1] = lrow0; ml[2] = mrow1; ml[3] = lrow1;
    }
    __syncthreads();
    if (nh == 0) {
        const float* src = (const float*)(sm + F2_ST0) + qm * 2048 + lane * 64;
        const float* ml = (const float*)(sm + F2_ML) + qm * 128 + lane * 4;
        const float m1 = ml[0], l1 = ml[1], m1b = ml[2], l1b = ml[3];
        const float M0 = fmaxf(mrow0, m1);
        const float M1 = fmaxf(mrow1, m1b);
        const float a0 = ex2f(mrow0 - M0), b0 = ex2f(m1 - M0);
        const float a1 = ex2f(mrow1 - M1), b1 = ex2f(m1b - M1);
        const float inv0 = 1.0f / (lrow0 * a0 + l1 * b0);
        const float inv1 = 1.0f / (lrow1 * a1 + l1b * b1);

        const int r0 = q0 + qm * 16 + (lane >> 2);
        const int cbase = h * HD + (lane & 3) * 2;
#pragma unroll
        for (int nt = 0; nt < 16; ++nt) {
            const int c = cbase + nt * 8;
            float v0 = (oacc[nt][0] * a0 + src[nt * 4 + 0] * b0) * inv0;
            float v1 = (oacc[nt][1] * a0 + src[nt * 4 + 1] * b0) * inv0;
            float v2 = (oacc[nt][2] * a1 + src[nt * 4 + 2] * b1) * inv1;
            float v3 = (oacc[nt][3] * a1 + src[nt * 4 + 3] * b1) * inv1;
            uint32_t hw, lw;
            split2(v0, v1, hw, lw);
            *(unsigned int*)(oh_ + (size_t)r0 * DIMN + c) = hw;
            *(unsigned int*)(ol_ + (size_t)r0 * DIMN + c) = lw;
            split2(v2, v3, hw, lw);
            *(unsigned int*)(oh_ + (size_t)(r0 + 8) * DIMN + c) = hw;
            *(unsigned int*)(ol_ + (size_t)(r0 + 8) * DIMN + c) = lw;
        }
    }
}

// ============================================================================
// launch
// ============================================================================
extern "C" void kernel_launch(void* const* d_in, const int* in_sizes, int n_in,
                              void* d_out, int out_size)
{
    const float* x  = (const float*)d_in[0];
    const float* Wq = (const float*)d_in[1];
    const float* bq = (const float*)d_in[2];
    const float* Wk = (const float*)d_in[3];
    const float* bk = (const float*)d_in[4];
    const float* Wv = (const float*)d_in[5];
    const float* bv = (const float*)d_in[6];
    const float* Wo = (const float*)d_in[7];
    const float* bo = (const float*)d_in[8];
    const float* gq = (const float*)d_in[9];
    const float* gk = (const float*)d_in[10];
    const float* cf = (const float*)d_in[11];
    const float* sf = (const float*)d_in[12];
    const float* ch = (const float*)d_in[13];
    const float* sh = (const float*)d_in[14];
    const float* cw = (const float*)d_in[15];
    const float* sw = (const float*)d_in[16];
    float* out = (float*)d_out;

    float *Qd, *Kd;
    unsigned short *qh, *ql, *kh, *kl, *vh, *vl, *oh, *ol, *xh, *xl;
    unsigned short *wqh, *wql, *wkh, *wkl, *wvh, *wvl, *woh, *wol;
    cudaGetSymbolAddress((void**)&Qd, g_Q);
    cudaGetSymbolAddress((void**)&Kd, g_K);
    cudaGetSymbolAddress((void**)&qh, g_qh);  cudaGetSymbolAddress((void**)&ql, g_ql);
    cudaGetSymbolAddress((void**)&kh, g_kh);  cudaGetSymbolAddress((void**)&kl, g_kl);
    cudaGetSymbolAddress((void**)&vh, g_vh);  cudaGetSymbolAddress((void**)&vl, g_vl);
    cudaGetSymbolAddress((void**)&oh, g_oh);  cudaGetSymbolAddress((void**)&ol, g_ol);
    cudaGetSymbolAddress((void**)&xh, g_xh);  cudaGetSymbolAddress((void**)&xl, g_xl);
    cudaGetSymbolAddress((void**)&wqh, g_wqh); cudaGetSymbolAddress((void**)&wql, g_wql);
    cudaGetSymbolAddress((void**)&wkh, g_wkh); cudaGetSymbolAddress((void**)&wkl, g_wkl);
    cudaGetSymbolAddress((void**)&wvh, g_wvh); cudaGetSymbolAddress((void**)&wvl, g_wvl);
    cudaGetSymbolAddress((void**)&woh, g_woh); cudaGetSymbolAddress((void**)&wol, g_wol);

    cudaFuncSetAttribute(gemm_tc,
                         cudaFuncAttributeMaxDynamicSharedMemorySize, GEMM_SMEM);
    cudaFuncSetAttribute(flash_tc2,
                         cudaFuncAttributeMaxDynamicSharedMemorySize, FLASH2_SMEM);

    const int NW = DIMN * DIMN;
    const int NXV = S_LEN * DIMN;
    const int NXT = S_PAD * DIMN;

    split_kernel<<<NXT / 512, 256>>>(x, xh, xl, NXV, NXT);
    split_kernel<<<NW / 512, 256>>>(Wq, wqh, wql, NW, NW);
    split_kernel<<<NW / 512, 256>>>(Wk, wkh, wkl, NW, NW);
    split_kernel<<<NW / 512, 256>>>(Wv, wvh, wvl, NW, NW);
    split_kernel<<<NW / 512, 256>>>(Wo, woh, wol, NW, NW);

    dim3 ggrid(DIMN / 128, S_PAD / 128);
    gemm_tc<<<ggrid, 256, GEMM_SMEM>>>(xh, xl, wqh, wql, bq, Qd, nullptr, nullptr, S_PAD);
    gemm_tc<<<ggrid, 256, GEMM_SMEM>>>(xh, xl, wkh, wkl, bk, Kd, nullptr, nullptr, S_PAD);
    gemm_tc<<<ggrid, 256, GEMM_SMEM>>>(xh, xl, wvh, wvl, bv, nullptr, vh, vl, S_PAD);

    rmsrope_kernel<<<S_LEN, 256>>>(Qd, Kd, gq, gk, cf, sf, ch, sh, cw, sw,
                                   qh, ql, kh, kl);

    flash_tc2<<<dim3(S_LEN / 64, NHEAD), 256, FLASH2_SMEM>>>(qh, ql, kh, kl, vh, vl, oh, ol);

    gemm_tc<<<ggrid, 256, GEMM_SMEM>>>(oh, ol, woh, wol, bo, out, nullptr, nullptr, S_LEN);
}

// round 15
// speedup vs baseline: 1.0066x; 1.0016x over previous
#include <cuda_runtime.h>
#include <cuda_bf16.h>
#include <cstdint>
#include <math.h>

// ---------------- problem constants ----------------
#define S_LEN 4032
#define S_PAD 4096
#define DIMN  1536
#define NHEAD 12
#define HD    128
#define FF    9
#define HHG   16
#define WWG   28
#define CF    22
#define CHH   21
#define CWW   21

#define QK_SCALE_LOG2E ((float)(1.4426950408889634 * 0.08838834764831845))

// ---------------- scratch ----------------
__device__ float g_Q[S_PAD * DIMN];
__device__ float g_K[S_PAD * DIMN];
__device__ unsigned short g_qh[S_PAD * DIMN], g_ql[S_PAD * DIMN];
__device__ unsigned short g_kh[S_PAD * DIMN], g_kl[S_PAD * DIMN];
__device__ unsigned short g_vh[S_PAD * DIMN], g_vl[S_PAD * DIMN];
__device__ unsigned short g_oh[S_PAD * DIMN], g_ol[S_PAD * DIMN];
__device__ unsigned short g_xh[S_PAD * DIMN], g_xl[S_PAD * DIMN];
__device__ unsigned short g_wqh[DIMN * DIMN], g_wql[DIMN * DIMN];
__device__ unsigned short g_wkh[DIMN * DIMN], g_wkl[DIMN * DIMN];
__device__ unsigned short g_wvh[DIMN * DIMN], g_wvl[DIMN * DIMN];
__device__ unsigned short g_woh[DIMN * DIMN], g_wol[DIMN * DIMN];

// ---------------- helpers ----------------
__device__ __forceinline__ uint32_t smem_to_u32(const void* p) {
    uint32_t a;
    asm("{ .reg .u64 t; cvta.to.shared.u64 t, %1; cvt.u32.u64 %0, t; }" : "=r"(a) : "l"(p));
    return a;
}
#define SWZ128(off) ((off) ^ (((off) >> 3) & 0x70))

__device__ __forceinline__ void ldsm_x4(uint32_t* r, uint32_t addr) {
    asm volatile("ldmatrix.sync.aligned.m8n8.x4.shared.b16 {%0,%1,%2,%3}, [%4];"
                 : "=r"(r[0]), "=r"(r[1]), "=r"(r[2]), "=r"(r[3]) : "r"(addr));
}
__device__ __forceinline__ void ldsm_x2(uint32_t* r, uint32_t addr) {
    asm volatile("ldmatrix.sync.aligned.m8n8.x2.shared.b16 {%0,%1}, [%2];"
                 : "=r"(r[0]), "=r"(r[1]) : "r"(addr));
}
__device__ __forceinline__ void ldsm_x2_t(uint32_t* r, uint32_t addr) {
    asm volatile("ldmatrix.sync.aligned.m8n8.x2.trans.shared.b16 {%0,%1}, [%2];"
                 : "=r"(r[0]), "=r"(r[1]) : "r"(addr));
}
__device__ __forceinline__ void mma_bf16(float* c, const uint32_t* a, const uint32_t* b) {
    asm volatile("mma.sync.aligned.m16n8k16.row.col.f32.bf16.bf16.f32 "
                 "{%0,%1,%2,%3}, {%4,%5,%6,%7}, {%8,%9}, {%0,%1,%2,%3};"
                 : "+f"(c[0]), "+f"(c[1]), "+f"(c[2]), "+f"(c[3])
                 : "r"(a[0]), "r"(a[1]), "r"(a[2]), "r"(a[3]), "r"(b[0]), "r"(b[1]));
}
__device__ __forceinline__ float ex2f(float x) {
    float y; asm("ex2.approx.f32 %0, %1;" : "=f"(y) : "f"(x)); return y;
}
__device__ __forceinline__ uint32_t pack_bf2(float x, float y) {
    uint32_t d; asm("cvt.rn.bf16x2.f32 %0, %1, %2;" : "=r"(d) : "f"(y), "f"(x)); return d;
}
__device__ __forceinline__ void split2(float x, float y, uint32_t& hi, uint32_t& lo) {
    hi = pack_bf2(x, y);
    float hx = __uint_as_float(hi << 16);
    float hy = __uint_as_float(hi & 0xffff0000u);
    lo = pack_bf2(x - hx, y - hy);
}
__device__ __forceinline__ void cp_async16(uint32_t saddr, const void* g) {
    asm volatile("cp.async.cg.shared.global [%0], [%1], 16;" :: "r"(saddr), "l"(g) : "memory");
}

// ============================================================================
// split fp32 -> bf16 hi/lo
// ============================================================================
__global__ __launch_bounds__(256) void split_kernel(
    const float* __restrict__ src, unsigned short* __restrict__ hi,
    unsigned short* __restrict__ lo, int n_valid, int n_total)
{
    int i = (blockIdx.x * 256 + threadIdx.x) * 2;
    if (i >= n_total) return;
    float2 v = (i < n_valid) ? *(const float2*)(src + i) : make_float2(0.f, 0.f);
    uint32_t h, l;
    split2(v.x, v.y, h, l);
    *(unsigned int*)(hi + i) = h;
    *(unsigned int*)(lo + i) = l;
}

// ============================================================================
// mma.sync bf16x3 GEMM (unchanged from R4)
// ============================================================================
#define SM_AH  0
#define SM_AL  16384
#define SM_BH  32768
#define SM_BL  49152
#define GEMM_SMEM 65536
#define NCHUNK (DIMN / 64)

__global__ __launch_bounds__(256, 2) void gemm_tc(
    const unsigned short* __restrict__ Ahi, const unsigned short* __restrict__ Alo,
    const unsigned short* __restrict__ Bhi, const unsigned short* __restrict__ Blo,
    const float* __restrict__ bias, float* __restrict__ C,
    unsigned short* __restrict__ Chi, unsigned short* __restrict__ Clo, int Mvalid)
{
    extern __shared__ __align__(1024) char smem[];
    const uint32_t sb = smem_to_u32(smem);
    const int tid  = threadIdx.x;
    const int lane = tid & 31;
    const int wid  = tid >> 5;
    const int wm   = wid & 1;
    const int wn   = wid >> 1;
    const int bm = blockIdx.y * 128;
    const int bn = blockIdx.x * 128;

    const int r0 = tid >> 3;
    const int c8 = tid & 7;
    const uint32_t st_off = SWZ128((uint32_t)(r0 * 128 + c8 * 16));

    uint32_t aoff[4], akey[4];
#pragma unroll
    for (int mf = 0; mf < 4; ++mf) {
        int arow = wm * 64 + mf * 16 + (lane & 15);
        aoff[mf] = (uint32_t)(arow * 128);
        akey[mf] = (uint32_t)((arow & 7) << 4);
    }
    uint32_t boff[4], bkey[4];
    {
        int l = lane & 15;
#pragma unroll
        for (int nf = 0; nf < 4; ++nf) {
            int brow = wn * 32 + nf * 8 + (l & 7);
            boff[nf] = (uint32_t)(brow * 128);
            bkey[nf] = (uint32_t)((brow & 7) << 4);
        }
    }
    const uint32_t abit = (uint32_t)((lane >> 4) << 4);
    const uint32_t bbit = (uint32_t)((((lane & 15) >> 3) & 1) << 4);

    float acc[4][4][4];
#pragma unroll
    for (int mf = 0; mf < 4; ++mf)
#pragma unroll
        for (int nf = 0; nf < 4; ++nf)
#pragma unroll
            for (int e = 0; e < 4; ++e) acc[mf][nf][e] = 0.f;

    for (int chunk = 0; chunk < NCHUNK; ++chunk) {
        const int k0 = chunk * 64;
        __syncthreads();
        {
            const unsigned short* srcs[4] = {Ahi, Alo, Bhi, Blo};
            const int rowbase[4] = {bm, bm, bn, bn};
            const uint32_t dsts[4] = {SM_AH, SM_AL, SM_BH, SM_BL};
#pragma unroll
            for (int t = 0; t < 4; ++t) {
                const unsigned short* s = srcs[t] + (size_t)(rowbase[t] + r0) * DIMN + k0 + c8 * 8;
                char* d = smem + dsts[t] + st_off;
#pragma unroll
                for (int i = 0; i < 4; ++i)
                    *(uint4*)(d + i * 4096) = *(const uint4*)(s + (size_t)(i * 32) * DIMN);
            }
        }
        __syncthreads();

#pragma unroll
        for (int ks = 0; ks < 4; ++ks) {
            const uint32_t kb = (uint32_t)(ks * 32);
            uint32_t bh[4][2], bl[4][2];
#pragma unroll
            for (int nf = 0; nf < 4; ++nf) {
                uint32_t ad = sb + SM_BH + boff[nf] + ((kb + bbit) ^ bkey[nf]);
                ldsm_x2(bh[nf], ad);
                ldsm_x2(bl[nf], ad + (SM_BL - SM_BH));
            }
#pragma unroll
            for (int mf = 0; mf < 4; ++mf) {
                uint32_t ah[4], al[4];
                uint32_t ad = sb + SM_AH + aoff[mf] + ((kb + abit) ^ akey[mf]);
                ldsm_x4(ah, ad);
                ldsm_x4(al, ad + (SM_AL - SM_AH));
#pragma unroll
                for (int nf = 0; nf < 4; ++nf) {
                    mma_bf16(acc[mf][nf], ah, bh[nf]);
                    mma_bf16(acc[mf][nf], ah, bl[nf]);
                    mma_bf16(acc[mf][nf], al, bh[nf]);
                }
            }
        }
    }

    const int row0 = bm + wm * 64 + (lane >> 2);
    const int col0 = bn + wn * 32 + (lane & 3) * 2;
#pragma unroll
    for (int nf = 0; nf < 4; ++nf) {
        const int c = col0 + nf * 8;
        const float2 bb = *(const float2*)(bias + c);
#pragma unroll
        for (int mf = 0; mf < 4; ++mf) {
            const int r = row0 + mf * 16;
            if (Chi) {
                uint32_t h, l;
                if (r < Mvalid) {
                    split2(acc[mf][nf][0] + bb.x, acc[mf][nf][1] + bb.y, h, l);
                    *(unsigned int*)(Chi + (size_t)r * DIMN + c) = h;
                    *(unsigned int*)(Clo + (size_t)r * DIMN + c) = l;
                }
                if (r + 8 < Mvalid) {
                    split2(acc[mf][nf][2] + bb.x, acc[mf][nf][3] + bb.y, h, l);
                    *(unsigned int*)(Chi + (size_t)(r + 8) * DIMN + c) = h;
                    *(unsigned int*)(Clo + (size_t)(r + 8) * DIMN + c) = l;
                }
            } else {
                if (r < Mvalid) {
                    float2 v; v.x = acc[mf][nf][0] + bb.x; v.y = acc[mf][nf][1] + bb.y;
                    *(float2*)(C + (size_t)r * DIMN + c) = v;
                }
                if (r + 8 < Mvalid) {
                    float2 v; v.x = acc[mf][nf][2] + bb.x; v.y = acc[mf][nf][3] + bb.y;
                    *(float2*)(C + (size_t)(r + 8) * DIMN + c) = v;
                }
            }
        }
    }
}

// ============================================================================
// Fused RMSNorm + 3D RoPE (unchanged)
// ============================================================================
__global__ __launch_bounds__(256) void rmsrope_kernel(
    const float* __restrict__ Qm, const float* __restrict__ Km,
    const float* __restrict__ gq, const float* __restrict__ gk,
    const float* __restrict__ cf, const float* __restrict__ sf,
    const float* __restrict__ ch, const float* __restrict__ sh,
    const float* __restrict__ cw, const float* __restrict__ sw,
    unsigned short* __restrict__ qh, unsigned short* __restrict__ ql,
    unsigned short* __restrict__ kh, unsigned short* __restrict__ kl)
{
    const int s = blockIdx.x;
    const int tid = threadIdx.x;
    const int f  = s / (HHG * WWG);
    const int rm = s - f * (HHG * WWG);
    const int hh = rm / WWG;
    const int ww = rm - hh * WWG;

    float co[3], si[3];
#pragma unroll
    for (int p = 0; p < 3; ++p) {
        int c = (tid * 3 + p) & 63;
        if (c < CF)            { co[p] = cf[f  * CF  + c];              si[p] = sf[f  * CF  + c]; }
        else if (c < CF + CHH) { co[p] = ch[hh * CHH + (c - CF)];       si[p] = sh[hh * CHH + (c - CF)]; }
        else                   { co[p] = cw[ww * CWW + (c - CF - CHH)]; si[p] = sw[ww * CWW + (c - CF - CHH)]; }
    }

    __shared__ float red[8];
    __shared__ float bcast;

    for (int which = 0; which < 2; ++which) {
        const float* T = which ? Km : Qm;
        const float* g = which ? gk : gq;
        unsigned short* oh = which ? kh : qh;
        unsigned short* ol = which ? kl : ql;
        const float post = which ? 1.0f : QK_SCALE_LOG2E;
        const size_t base = (size_t)s * DIMN + tid * 6;

        float v[6];
#pragma unroll
        for (int p = 0; p < 3; ++p) {
            float2 t = *(const float2*)(T + base + 2 * p);
            v[2 * p] = t.x; v[2 * p + 1] = t.y;
        }
        float ss = 0.f;
#pragma unroll
        for (int e = 0; e < 6; ++e) ss += v[e] * v[e];
        for (int off = 16; off; off >>= 1) ss += __shfl_xor_sync(0xffffffffu, ss, off);
        if ((tid & 31) == 0) red[tid >> 5] = ss;
        __syncthreads();
        if (tid < 32) {
            float t = (tid < 8) ? red[tid] : 0.f;
            for (int off = 4; off; off >>= 1) t += __shfl_xor_sync(0xffffffffu, t, off);
            if (tid == 0) bcast = t;
        }
        __syncthreads();
        const float rinv = rsqrtf(bcast * (1.0f / DIMN) + 1e-6f);

#pragma unroll
        for (int p = 0; p < 3; ++p) {
            float e = v[2 * p]     * rinv * g[tid * 6 + 2 * p];
            float o = v[2 * p + 1] * rinv * g[tid * 6 + 2 * p + 1];
            float rx = (e * co[p] - o * si[p]) * post;
            float ry = (e * si[p] + o * co[p]) * post;
            uint32_t hw, lw;
            split2(rx, ry, hw, lw);
            *(unsigned int*)(oh + base + 2 * p) = hw;
            *(unsigned int*)(ol + base + 2 * p) = lw;
        }
        __syncthreads();
    }
}

// ============================================================================
// Flash attention, HMMA bf16x3. 256 threads, 2 CTAs/SM (4 warps/SMSP).
// BQ=64, BK=32. 8 warps = 4 q-tiles(16 rows) x 2 key-halves(16 of 32 keys).
// Q hi/lo resident in smem (32KB); K/V hi/lo double-buffered (2x32KB).
// Per-warp online softmax over its key subset; pairwise m/l/O merge at end.
// ============================================================================
#define F2_QH   0
#define F2_QL   16384
#define F2_ST0  32768
#define F2_KH   0
#define F2_KL   8192
#define F2_VH   16384
#define F2_VL   24576
#define F2_ML   98304
#define FLASH2_SMEM (98304 + 2048)
#define NKT2 (S_LEN / 32)   // 126

__global__ __launch_bounds__(256, 2) void flash_tc2(
    const unsigned short* __restrict__ qh_, const unsigned short* __restrict__ ql_,
    const unsigned short* __restrict__ kh_, const unsigned short* __restrict__ kl_,
    const unsigned short* __restrict__ vh_, const unsigned short* __restrict__ vl_,
    unsigned short* __restrict__ oh_, unsigned short* __restrict__ ol_)
{
    extern __shared__ __align__(1024) char sm[];
    const uint32_t sb = smem_to_u32(sm);
    const int tid = threadIdx.x;
    const int lane = tid & 31;
    const int w = tid >> 5;         // 0..7
    const int nh = w & 1;           // key-half
    const int qm = w >> 1;          // q-tile 0..3
    const int l15 = lane & 15;
    const int h = blockIdx.y;
    const int q0 = blockIdx.x * 64;

    // ---- stage Q (hi/lo) resident: 64 rows x 128 cols, 2 chunks of [64][64c] ----
    {
        const unsigned short* srcs[2] = {qh_, ql_};
#pragma unroll
        for (int hl = 0; hl < 2; ++hl) {
            const unsigned short* s = srcs[hl];
#pragma unroll
            for (int i = 0; i < 4; ++i) {
                int idx = tid + i * 256;
                int qr = idx >> 4, c16 = idx & 15;
                uint4 v = *(const uint4*)(s + (size_t)(q0 + qr) * DIMN + h * HD + c16 * 8);
                uint32_t off = (uint32_t)(hl * 16384 + (c16 >> 3) * 8192)
                             + SWZ128((uint32_t)(qr * 128 + (c16 & 7) * 16));
                *(uint4*)(sm + off) = v;
            }
        }
    }

    // ---- K/V stage loader: 4 tiles x [32 rows][128 cols], 2 chunks of 4KB ----
    const int srow = tid >> 3;      // 0..31
    const int sc8 = tid & 7;
    const uint32_t so0 = SWZ128((uint32_t)(srow * 128 + sc8 * 16));
    auto issue_stage = [&](int kt, int st) {
        const int key0 = kt * 32;
        const unsigned short* srcs[4] = {kh_, kl_, vh_, vl_};
        uint32_t base = sb + (uint32_t)(F2_ST0 + st * 32768);
#pragma unroll
        for (int t = 0; t < 4; ++t) {
            const unsigned short* sp = srcs[t] + (size_t)(key0 + srow) * DIMN + h * HD;
            cp_async16(base + (uint32_t)(t * 8192) + so0, sp + sc8 * 8);
            cp_async16(base + (uint32_t)(t * 8192 + 4096) + so0, sp + (sc8 + 8) * 8);
        }
        asm volatile("cp.async.commit_group;" ::: "memory");
    };

    float oacc[16][4];
#pragma unroll
    for (int nt = 0; nt < 16; ++nt)
#pragma unroll
        for (int e = 0; e < 4; ++e) oacc[nt][e] = 0.f;
    float mrow0 = -1e30f, mrow1 = -1e30f, lrow0 = 0.f, lrow1 = 0.f;

    // Q addressing
    const int qrow = qm * 16 + l15;
    const uint32_t qrowb = (uint32_t)(qrow * 128);
    const uint32_t qc8sel = (uint32_t)(lane >> 4);

    issue_stage(0, 0);

    for (int kt = 0; kt < NKT2; ++kt) {
        const int st = kt & 1;
        if (kt < NKT2 - 1) {
            issue_stage(kt + 1, st ^ 1);
            asm volatile("cp.async.wait_group 1;" ::: "memory");
        } else {
            asm volatile("cp.async.wait_group 0;" ::: "memory");
        }
        __syncthreads();

        const uint32_t stb = sb + (uint32_t)(F2_ST0 + st * 32768);

        // ---- scores: 16 q-rows x 16 k-cols (this warp's half) ----
        float sc[2][4];
        sc[0][0] = sc[0][1] = sc[0][2] = sc[0][3] = 0.f;
        sc[1][0] = sc[1][1] = sc[1][2] = sc[1][3] = 0.f;

#pragma unroll
        for (int ks = 0; ks < 8; ++ks) {
            const uint32_t qaddr = sb + (uint32_t)((ks >> 2) * 8192)
                + SWZ128(qrowb + (uint32_t)(((ks & 3) * 2 + qc8sel) * 16));
            uint32_t qh4[4], ql4[4];
            ldsm_x4(qh4, qaddr);
            ldsm_x4(ql4, qaddr + F2_QL);
            const uint32_t kchunk = (uint32_t)((ks >> 2) * 4096);
            const uint32_t kc8 = (uint32_t)(((ks & 3) * 2 + ((l15 >> 3) & 1)) * 16);
#pragma unroll
            for (int nt = 0; nt < 2; ++nt) {
                const uint32_t krow = (uint32_t)((nh * 16 + nt * 8 + (l15 & 7)) * 128);
                uint32_t addr = stb + F2_KH + kchunk + SWZ128(krow + kc8);
                uint32_t bh[2], bl[2];
                ldsm_x2(bh, addr);
                ldsm_x2(bl, addr + (F2_KL - F2_KH));
                mma_bf16(sc[nt], qh4, bh);
                mma_bf16(sc[nt], qh4, bl);
                mma_bf16(sc[nt], ql4, bh);
            }
        }

        // ---- online softmax (log2 units), per-warp key subset ----
        float mx0 = fmaxf(fmaxf(sc[0][0], sc[0][1]), fmaxf(sc[1][0], sc[1][1]));
        float mx1 = fmaxf(fmaxf(sc[0][2], sc[0][3]), fmaxf(sc[1][2], sc[1][3]));
        mx0 = fmaxf(mx0, __shfl_xor_sync(0xffffffffu, mx0, 1));
        mx0 = fmaxf(mx0, __shfl_xor_sync(0xffffffffu, mx0, 2));
        mx1 = fmaxf(mx1, __shfl_xor_sync(0xffffffffu, mx1, 1));
        mx1 = fmaxf(mx1, __shfl_xor_sync(0xffffffffu, mx1, 2));
        const float mn0 = fmaxf(mrow0, mx0);
        const float mn1 = fmaxf(mrow1, mx1);
        const float al0 = ex2f(mrow0 - mn0);
        const float al1 = ex2f(mrow1 - mn1);
        mrow0 = mn0; mrow1 = mn1;
        float rs0 = 0.f, rs1 = 0.f;
#pragma unroll
        for (int nt = 0; nt < 2; ++nt) {
            sc[nt][0] = ex2f(sc[nt][0] - mn0); rs0 += sc[nt][0];
            sc[nt][1] = ex2f(sc[nt][1] - mn0); rs0 += sc[nt][1];
            sc[nt][2] = ex2f(sc[nt][2] - mn1); rs1 += sc[nt][2];
            sc[nt][3] = ex2f(sc[nt][3] - mn1); rs1 += sc[nt][3];
        }
        rs0 += __shfl_xor_sync(0xffffffffu, rs0, 1);
        rs0 += __shfl_xor_sync(0xffffffffu, rs0, 2);
        rs1 += __shfl_xor_sync(0xffffffffu, rs1, 1);
        rs1 += __shfl_xor_sync(0xffffffffu, rs1, 2);
        lrow0 = lrow0 * al0 + rs0;
        lrow1 = lrow1 * al1 + rs1;
        if (al0 != 1.0f || al1 != 1.0f) {
#pragma unroll
            for (int nt = 0; nt < 16; ++nt) {
                oacc[nt][0] *= al0; oacc[nt][1] *= al0;
                oacc[nt][2] *= al1; oacc[nt][3] *= al1;
            }
        }

        // ---- pack P (16x16) into one A-frag group (hi/lo) ----
        uint32_t pah[4], pal[4];
        split2(sc[0][0], sc[0][1], pah[0], pal[0]);
        split2(sc[0][2], sc[0][3], pah[1], pal[1]);
        split2(sc[1][0], sc[1][1], pah[2], pal[2]);
        split2(sc[1][2], sc[1][3], pah[3], pal[3]);

        // ---- O += P @ V (this warp's 16 keys) ----
        const uint32_t vrow = (uint32_t)((nh * 16 + ((l15 >> 3) & 1) * 8 + (l15 & 7)) * 128);
#pragma unroll
        for (int nt = 0; nt < 16; ++nt) {
            uint32_t addr = stb + F2_VH + (uint32_t)((nt >> 3) * 4096)
                          + SWZ128(vrow + (uint32_t)((nt & 7) * 16));
            uint32_t bh[2], bl[2];
            ldsm_x2_t(bh, addr);
            ldsm_x2_t(bl, addr + (F2_VL - F2_VH));
            mma_bf16(oacc[nt], pah, bh);
            mma_bf16(oacc[nt], pah, bl);
            mma_bf16(oacc[nt], pal, bh);
        }
        __syncthreads();
    }

    // ---- merge key-half pairs: nh=1 publishes, nh=0 merges & writes ----
    __syncthreads();
    if (nh == 1) {
        float* dst = (float*)(sm + F2_ST0) + qm * 2048 + lane * 64;
#pragma unroll
        for (int nt = 0; nt < 16; ++nt) {
            dst[nt * 4 + 0] = oacc[nt][0];
            dst[nt * 4 + 1] = oacc[nt][1];
            dst[nt * 4 + 2] = oacc[nt][2];
            dst[nt * 4 + 3] = oacc[nt][3];
        }
        float* ml = (float*)(sm + F2_ML) + qm * 128 + lane * 4;
        ml[0] = mrow0; ml[1] = lrow0; ml[2] = mrow1; ml[3] = lrow1;
    }
    __syncthreads();
    if (nh == 0) {
        const float* src = (const float*)(sm + F2_ST0) + qm * 2048 + lane * 64;
        const float* ml = (const float*)(sm + F2_ML) + qm * 128 + lane * 4;
        const float m1 = ml[0], l1 = ml[1], m1b = ml[2], l1b = ml[3];
        const float M0 = fmaxf(mrow0, m1);
        const float M1 = fmaxf(mrow1, m1b);
        const float a0 = ex2f(mrow0 - M0), b0 = ex2f(m1 - M0);
        const float a1 = ex2f(mrow1 - M1), b1 = ex2f(m1b - M1);
        const float inv0 = 1.0f / (lrow0 * a0 + l1 * b0);
        const float inv1 = 1.0f / (lrow1 * a1 + l1b * b1);

        const int r0 = q0 + qm * 16 + (lane >> 2);
        const int cbase = h * HD + (lane & 3) * 2;
#pragma unroll
        for (int nt = 0; nt < 16; ++nt) {
            const int c = cbase + nt * 8;
            float v0 = (oacc[nt][0] * a0 + src[nt * 4 + 0] * b0) * inv0;
            float v1 = (oacc[nt][1] * a0 + src[nt * 4 + 1] * b0) * inv0;
            float v2 = (oacc[nt][2] * a1 + src[nt * 4 + 2] * b1) * inv1;
            float v3 = (oacc[nt][3] * a1 + src[nt * 4 + 3] * b1) * inv1;
            uint32_t hw, lw;
            split2(v0, v1, hw, lw);
            *(unsigned int*)(oh_ + (size_t)r0 * DIMN + c) = hw;
            *(unsigned int*)(ol_ + (size_t)r0 * DIMN + c) = lw;
            split2(v2, v3, hw, lw);
            *(unsigned int*)(oh_ + (size_t)(r0 + 8) * DIMN + c) = hw;
            *(unsigned int*)(ol_ + (size_t)(r0 + 8) * DIMN + c) = lw;
        }
    }
}

// ============================================================================
// launch
// ============================================================================
extern "C" void kernel_launch(void* const* d_in, const int* in_sizes, int n_in,
                              void* d_out, int out_size)
{
    const float* x  = (const float*)d_in[0];
    const float* Wq = (const float*)d_in[1];
    const float* bq = (const float*)d_in[2];
    const float* Wk = (const float*)d_in[3];
    const float* bk = (const float*)d_in[4];
    const float* Wv = (const float*)d_in[5];
    const float* bv = (const float*)d_in[6];
    const float* Wo = (const float*)d_in[7];
    const float* bo = (const float*)d_in[8];
    const float* gq = (const float*)d_in[9];
    const float* gk = (const float*)d_in[10];
    const float* cf = (const float*)d_in[11];
    const float* sf = (const float*)d_in[12];
    const float* ch = (const float*)d_in[13];
    const float* sh = (const float*)d_in[14];
    const float* cw = (const float*)d_in[15];
    const float* sw = (const float*)d_in[16];
    float* out = (float*)d_out;

    float *Qd, *Kd;
    unsigned short *qh, *ql, *kh, *kl, *vh, *vl, *oh, *ol, *xh, *xl;
    unsigned short *wqh, *wql, *wkh, *wkl, *wvh, *wvl, *woh, *wol;
    cudaGetSymbolAddress((void**)&Qd, g_Q);
    cudaGetSymbolAddress((void**)&Kd, g_K);
    cudaGetSymbolAddress((void**)&qh, g_qh);  cudaGetSymbolAddress((void**)&ql, g_ql);
    cudaGetSymbolAddress((void**)&kh, g_kh);  cudaGetSymbolAddress((void**)&kl, g_kl);
    cudaGetSymbolAddress((void**)&vh, g_vh);  cudaGetSymbolAddress((void**)&vl, g_vl);
    cudaGetSymbolAddress((void**)&oh, g_oh);  cudaGetSymbolAddress((void**)&ol, g_ol);
    cudaGetSymbolAddress((void**)&xh, g_xh);  cudaGetSymbolAddress((void**)&xl, g_xl);
    cudaGetSymbolAddress((void**)&wqh, g_wqh); cudaGetSymbolAddress((void**)&wql, g_wql);
    cudaGetSymbolAddress((void**)&wkh, g_wkh); cudaGetSymbolAddress((void**)&wkl, g_wkl);
    cudaGetSymbolAddress((void**)&wvh, g_wvh); cudaGetSymbolAddress((void**)&wvl, g_wvl);
    cudaGetSymbolAddress((void**)&woh, g_woh); cudaGetSymbolAddress((void**)&wol, g_wol);

    cudaFuncSetAttribute(gemm_tc,
                         cudaFuncAttributeMaxDynamicSharedMemorySize, GEMM_SMEM);
    cudaFuncSetAttribute(flash_tc2,
                         cudaFuncAttributeMaxDynamicSharedMemorySize, FLASH2_SMEM);

    const int NW = DIMN * DIMN;
    const int NXV = S_LEN * DIMN;
    const int NXT = S_PAD * DIMN;

    split_kernel<<<NXT / 512, 256>>>(x, xh, xl, NXV, NXT);
    split_kernel<<<NW / 512, 256>>>(Wq, wqh, wql, NW, NW);
    split_kernel<<<NW / 512, 256>>>(Wk, wkh, wkl, NW, NW);
    split_kernel<<<NW / 512, 256>>>(Wv, wvh, wvl, NW, NW);
    split_kernel<<<NW / 512, 256>>>(Wo, woh, wol, NW, NW);

    dim3 ggrid(DIMN / 128, S_PAD / 128);
    gemm_tc<<<ggrid, 256, GEMM_SMEM>>>(xh, xl, wqh, wql, bq, Qd, nullptr, nullptr, S_PAD);
    gemm_tc<<<ggrid, 256, GEMM_SMEM>>>(xh, xl, wkh, wkl, bk, Kd, nullptr, nullptr, S_PAD);
    gemm_tc<<<ggrid, 256, GEMM_SMEM>>>(xh, xl, wvh, wvl, bv, nullptr, vh, vl, S_PAD);

    rmsrope_kernel<<<S_LEN, 256>>>(Qd, Kd, gq, gk, cf, sf, ch, sh, cw, sw,
                                   qh, ql, kh, kl);

    flash_tc2<<<dim3(S_LEN / 64, NHEAD), 256, FLASH2_SMEM>>>(qh, ql, kh, kl, vh, vl, oh, ol);

    gemm_tc<<<ggrid, 256, GEMM_SMEM>>>(oh, ol, woh, wol, bo, out, nullptr, nullptr, S_LEN);
}